// round 10
// baseline (speedup 1.0000x reference)
#include <cuda_runtime.h>
#include <cstdint>
#include <cstddef>

#define Bn   2
#define Ln   2048
#define Hn   768
#define DIn  1536
#define Nn   16
#define Rn   48
#define RnP  64          /* dt K padded to 64 for BK=32 */
#define BLn  (Bn*Ln)     /* 4096 */
#define SP   (Rn + 2*Nn) /* 80 */

// -------- scratch (static device globals; zero-initialized at load) --------
__device__ float g_proj [(size_t)BLn * 2 * DIn];  // in_proj output (h | gate)
__device__ float g_h    [(size_t)BLn * DIn];      // conv+silu output
__device__ float g_ssm  [(size_t)BLn * SP];       // x_proj output (dt_raw|B|C)
__device__ float g_dtraw[(size_t)BLn * RnP];      // tf32 dt_raw, K-padded (cols 48..63 stay 0)
__device__ float g_dt   [(size_t)BLn * DIn];      // softplus(dt)
__device__ float g_y    [(size_t)BLn * DIn];      // scan output (tf32-rounded)
__device__ float g_xr   [(size_t)BLn * Hn];       // tf32-rounded x
__device__ float g_w1   [(size_t)Hn * 2 * DIn];   // in_proj_w^T  [3072][768], tf32
__device__ float g_w2   [(size_t)DIn * RnP];      // dt_proj_w^T  [1536][64],  tf32 (pad 0)
__device__ float g_w3   [(size_t)DIn * Hn];       // out_proj_w^T [768][1536], tf32

__device__ __forceinline__ float sigmoidf_(float x) { return 1.f / (1.f + __expf(-x)); }
__device__ __forceinline__ uint32_t f2tf(float f) {
    uint32_t u; asm("cvt.rna.tf32.f32 %0, %1;" : "=r"(u) : "f"(f)); return u;
}
__device__ __forceinline__ float roundtf(float f) { return __uint_as_float(f2tf(f)); }
__device__ __forceinline__ float softplusf_(float x) {
    return fmaxf(x, 0.f) + log1pf(__expf(-fabsf(x)));
}
__device__ __forceinline__ void cp16ca(uint32_t sa, const void* g) {
    asm volatile("cp.async.ca.shared.global [%0], [%1], 16;\n" :: "r"(sa), "l"(g));
}
__device__ __forceinline__ void cp_commit() {
    asm volatile("cp.async.commit_group;\n");
}
template<int NN>
__device__ __forceinline__ void cp_wait() {
    asm volatile("cp.async.wait_group %0;\n" :: "n"(NN));
}
__device__ __forceinline__ uint32_t smem_u32(const void* p) {
    return (uint32_t)__cvta_generic_to_shared(p);
}
__device__ __forceinline__ void ldsm_x4(uint32_t& r0, uint32_t& r1, uint32_t& r2,
                                        uint32_t& r3, uint32_t a) {
    asm volatile("ldmatrix.sync.aligned.m8n8.x4.shared.b16 {%0,%1,%2,%3}, [%4];"
                 : "=r"(r0), "=r"(r1), "=r"(r2), "=r"(r3) : "r"(a));
}

// ============================================================================
// Fused preprocessing: one launch covering
//   [0, NBX)                 : tf32-round x -> g_xr (float4/thread)
//   [NBX, +NBW1)             : transpose+round in_proj_w  -> g_w1
//   [.., +NBW2)              : transpose+round dt_proj_w  -> g_w2 (stride RnP)
//   [.., +NBW3)              : transpose+round out_proj_w -> g_w3
//   [.., +NBZ)               : zero g_ssm
// ============================================================================
#define S0   ((size_t)BLn * Hn)
#define NBX  ((int)(S0 / 4 / 256))                          /* 3072 */
#define NBW1 ((2 * DIn / 32) * (Hn / 32))                    /* 2304 */
#define NBW2 ((DIn / 32) * ((Rn + 31) / 32))                 /* 96   */
#define NBW3 ((Hn / 32) * (DIn / 32))                        /* 1152 */
#define NBZ  ((int)((BLn * SP / 4 + 255) / 256))             /* 320  */
#define NB_PRE (NBX + NBW1 + NBW2 + NBW3 + NBZ)

__device__ __forceinline__ void transpose_tile(
    const float* __restrict__ src, float* __restrict__ dst,
    int R, int C, int Rstride, int bx, int by, float (*t)[33])
{
    const int tx = threadIdx.x & 31;
    const int ty = threadIdx.x >> 5;
#pragma unroll
    for (int i = 0; i < 32; i += 8) {
        int r = (by << 5) + ty + i, c = (bx << 5) + tx;
        if (r < R && c < C) t[ty + i][tx] = src[(size_t)r * C + c];
    }
    __syncthreads();
#pragma unroll
    for (int i = 0; i < 32; i += 8) {
        int r = (bx << 5) + ty + i, c = (by << 5) + tx;
        if (r < C && c < R) dst[(size_t)r * Rstride + c] = roundtf(t[tx][ty + i]);
    }
}

__global__ __launch_bounds__(256)
void fused_pre(const float* __restrict__ x,
               const float* __restrict__ in_proj_w,
               const float* __restrict__ dt_proj_w,
               const float* __restrict__ out_proj_w)
{
    __shared__ float t[32][33];
    int bid = blockIdx.x;

    if (bid < NBX) {
        size_t i = ((size_t)bid * 256 + threadIdx.x) * 4;
        float4 v = *(const float4*)(x + i);
        v.x = roundtf(v.x); v.y = roundtf(v.y); v.z = roundtf(v.z); v.w = roundtf(v.w);
        *(float4*)(g_xr + i) = v;
        return;
    }
    bid -= NBX;
    if (bid < NBW1) {
        const int nbx = 2 * DIn / 32;
        transpose_tile(in_proj_w, g_w1, Hn, 2 * DIn, Hn, bid % nbx, bid / nbx, t);
        return;
    }
    bid -= NBW1;
    if (bid < NBW2) {
        const int nbx = DIn / 32;
        transpose_tile(dt_proj_w, g_w2, Rn, DIn, RnP, bid % nbx, bid / nbx, t);
        return;
    }
    bid -= NBW2;
    if (bid < NBW3) {
        const int nbx = Hn / 32;
        transpose_tile(out_proj_w, g_w3, DIn, Hn, DIn, bid % nbx, bid / nbx, t);
        return;
    }
    bid -= NBW3;
    {
        size_t i = ((size_t)bid * 256 + threadIdx.x) * 4;
        if (i < (size_t)BLn * SP)
            *(float4*)&g_ssm[i] = make_float4(0.f, 0.f, 0.f, 0.f);
    }
}

__global__ __launch_bounds__(256)
void round_dtraw()
{
    int i = blockIdx.x * blockDim.x + threadIdx.x;   // over BLn*Rn
    if (i >= BLn * Rn) return;
    int row = i / Rn, col = i - row * Rn;
    g_dtraw[(size_t)row * RnP + col] = roundtf(g_ssm[(size_t)row * SP + col]);
}

// ============================================================================
// TF32 mma.sync GEMM: 128x128 CTA, 8 warps of 64x32, BK=32, 3-stage cp.async,
// ldmatrix x4 for both A and B.  C[M,N] = A[M,K](lda) @ Bt[N,K](ldb)^T.
// A,Bt pre-rounded tf32. EPI==1: C = softplus(C + bias[n]).
// ============================================================================
#define TG_STAGES 3
#define TG_TSZ (128 * 36)
#define TG_STG (2 * TG_TSZ)
#define TG_SMEM (TG_STAGES * TG_STG * 4)   /* 110592 bytes */

template<int EPI>
__global__ __launch_bounds__(256, 2)
void tgemm(const float* __restrict__ A, int lda,
           const float* __restrict__ Bt, int ldb,
           float* __restrict__ C, int N, int K,
           const float* __restrict__ bias)
{
    extern __shared__ float smem[];

    const int tid  = threadIdx.x;
    const int lane = tid & 31;
    const int warp = tid >> 5;
    const int wm   = warp >> 2;
    const int wn   = warp & 3;
    const int m0   = wm * 64;
    const int n0   = wn * 32;
    const int g    = lane >> 2;
    const int c    = lane & 3;

    const int bm = blockIdx.y << 7;
    const int bn = blockIdx.x << 7;

    const uint32_t smem0 = smem_u32(smem);

    uint32_t sOffA[4];
    const float* ApA[4];
    const float* BpA[4];
#pragma unroll
    for (int i = 0; i < 4; i++) {
        const int ch  = tid + (i << 8);
        const int row = ch >> 3;
        const int k4  = (ch & 7) << 2;
        sOffA[i] = (uint32_t)(row * 36 + k4) * 4;
        ApA[i] = A  + (size_t)(bm + row) * lda + k4;
        BpA[i] = Bt + (size_t)(bn + row) * ldb + k4;
    }

    const int arow = m0 + (lane & 7) + ((lane & 8) ? 8 : 0);
    const int acol = (lane & 16) ? 4 : 0;
    const uint32_t aBase = (uint32_t)(arow * 36 + acol) * 4;
    const int brow = n0 + (lane & 7) + ((lane & 16) ? 8 : 0);
    const int bcol = (lane & 8) ? 4 : 0;
    const uint32_t bBase = (uint32_t)(brow * 36 + bcol) * 4;

    float acc[4][4][4];
#pragma unroll
    for (int i = 0; i < 4; i++)
#pragma unroll
        for (int j = 0; j < 4; j++)
#pragma unroll
            for (int q = 0; q < 4; q++) acc[i][j][q] = 0.f;

    const int nk = K >> 5;

    auto load_stage = [&](int kt, int s) {
        const uint32_t stA = smem0 + (uint32_t)(s * TG_STG) * 4;
        const uint32_t stB = stA + TG_TSZ * 4;
        const int k0 = kt << 5;
#pragma unroll
        for (int i = 0; i < 4; i++) {
            cp16ca(stA + sOffA[i], ApA[i] + k0);
            cp16ca(stB + sOffA[i], BpA[i] + k0);
        }
    };
    auto compute = [&](int s) {
        const uint32_t stA = smem0 + (uint32_t)(s * TG_STG) * 4;
        const uint32_t stB = stA + TG_TSZ * 4;
#pragma unroll
        for (int ks = 0; ks < 4; ks++) {
            const uint32_t kb = (uint32_t)(ks << 3) * 4;
            uint32_t af[4][4], bf[4][2];
#pragma unroll
            for (int i = 0; i < 4; i++)
                ldsm_x4(af[i][0], af[i][1], af[i][2], af[i][3],
                        stA + aBase + (uint32_t)(i * 16 * 36) * 4 + kb);
#pragma unroll
            for (int jj = 0; jj < 2; jj++)
                ldsm_x4(bf[2 * jj][0], bf[2 * jj][1], bf[2 * jj + 1][0], bf[2 * jj + 1][1],
                        stB + bBase + (uint32_t)(jj * 16 * 36) * 4 + kb);
#pragma unroll
            for (int i = 0; i < 4; i++)
#pragma unroll
                for (int j = 0; j < 4; j++)
                    asm volatile(
                        "mma.sync.aligned.m16n8k8.row.col.f32.tf32.tf32.f32 "
                        "{%0,%1,%2,%3}, {%4,%5,%6,%7}, {%8,%9}, {%0,%1,%2,%3};\n"
                        : "+f"(acc[i][j][0]), "+f"(acc[i][j][1]),
                          "+f"(acc[i][j][2]), "+f"(acc[i][j][3])
                        : "r"(af[i][0]), "r"(af[i][1]), "r"(af[i][2]), "r"(af[i][3]),
                          "r"(bf[j][0]), "r"(bf[j][1]));
        }
    };

#pragma unroll
    for (int s = 0; s < TG_STAGES - 1; s++) {
        if (s < nk) load_stage(s, s);
        cp_commit();
    }
    for (int kt = 0; kt < nk; ++kt) {
        cp_wait<TG_STAGES - 2>();
        __syncthreads();
        const int nxt = kt + TG_STAGES - 1;
        if (nxt < nk) load_stage(nxt, nxt % TG_STAGES);
        cp_commit();
        compute(kt % TG_STAGES);
    }

#pragma unroll
    for (int i = 0; i < 4; i++) {
        const int r0 = bm + m0 + i * 16 + g;
#pragma unroll
        for (int j = 0; j < 4; j++) {
            const int col = bn + n0 + j * 8 + 2 * c;
            float v00 = acc[i][j][0], v01 = acc[i][j][1];
            float v10 = acc[i][j][2], v11 = acc[i][j][3];
            if (EPI == 1) {
                const float b0v = bias[col], b1v = bias[col + 1];
                v00 = softplusf_(v00 + b0v);
                v01 = softplusf_(v01 + b1v);
                v10 = softplusf_(v10 + b0v);
                v11 = softplusf_(v11 + b1v);
            }
            *(float2*)&C[(size_t)r0 * N + col]       = make_float2(v00, v01);
            *(float2*)&C[(size_t)(r0 + 8) * N + col] = make_float2(v10, v11);
        }
    }
}

// ============================================================================
// Depthwise causal conv (K=4) + bias + SiLU, 4 channels/thread.
// ============================================================================
__global__ __launch_bounds__(256)
void conv_silu(const float* __restrict__ proj,
               const float* __restrict__ cw,
               const float* __restrict__ cb,
               float* __restrict__ h)
{
    int idx = blockIdx.x * blockDim.x + threadIdx.x;
    int d4 = (idx % (DIn / 4)) << 2;
    int bt = idx / (DIn / 4);
    int t  = bt % Ln;

    const float* p = proj + (size_t)bt * (2 * DIn) + d4;
    const int s = 2 * DIn;
    float4 z  = make_float4(0.f, 0.f, 0.f, 0.f);
    float4 x0 = *(const float4*)p;
    float4 x1 = (t >= 1) ? *(const float4*)(p - s)     : z;
    float4 x2 = (t >= 2) ? *(const float4*)(p - 2 * s) : z;
    float4 x3 = (t >= 3) ? *(const float4*)(p - 3 * s) : z;
    float4 cbv = *(const float4*)(cb + d4);
    float4 w0 = *(const float4*)(cw + (d4 + 0) * 4);
    float4 w1 = *(const float4*)(cw + (d4 + 1) * 4);
    float4 w2 = *(const float4*)(cw + (d4 + 2) * 4);
    float4 w3 = *(const float4*)(cw + (d4 + 3) * 4);

    float4 o;
    o.x = fmaf(x3.x, w0.x, fmaf(x2.x, w0.y, fmaf(x1.x, w0.z, fmaf(x0.x, w0.w, cbv.x))));
    o.y = fmaf(x3.y, w1.x, fmaf(x2.y, w1.y, fmaf(x1.y, w1.z, fmaf(x0.y, w1.w, cbv.y))));
    o.z = fmaf(x3.z, w2.x, fmaf(x2.z, w2.y, fmaf(x1.z, w2.z, fmaf(x0.z, w2.w, cbv.z))));
    o.w = fmaf(x3.w, w3.x, fmaf(x2.w, w3.y, fmaf(x1.w, w3.z, fmaf(x0.w, w3.w, cbv.w))));
    o.x = o.x * sigmoidf_(o.x);
    o.y = o.y * sigmoidf_(o.y);
    o.z = o.z * sigmoidf_(o.z);
    o.w = o.w * sigmoidf_(o.w);
    *(float4*)(h + (size_t)bt * DIn + d4) = o;
}

// ============================================================================
// x_proj GEMM, split-K: ssm += h @ x_proj_w.
// ============================================================================
#define XKS 4
#define XKC (DIn / XKS)
__global__ __launch_bounds__(256)
void gemm_xproj(const float* __restrict__ A,
                const float* __restrict__ W)
{
    __shared__ float As[2][16][68];
    __shared__ float Ws[2][16][SP];

    const int tid = threadIdx.x;
    const int bm  = blockIdx.x << 6;
    const int k0  = blockIdx.y * XKC;
    const int tx  = tid & 15;
    const int ty  = tid >> 4;
    const int ar  = tid >> 2;
    const int ac4 = (tid & 3) << 2;

    float acc[4][5];
#pragma unroll
    for (int i = 0; i < 4; i++)
#pragma unroll
        for (int j = 0; j < 5; j++) acc[i][j] = 0.f;

    const float* Ap = A + (size_t)(bm + ar) * DIn + k0 + ac4;
    const int nk = XKC / 16;

    float4 aR; float wR[5];
    auto g2r = [&](int kt) {
        aR = *(const float4*)(Ap + kt * 16);
#pragma unroll
        for (int j = 0; j < 5; j++) {
            int e = tid + (j << 8);
            int k = e / SP, n2 = e % SP;
            wR[j] = W[(size_t)(k0 + kt * 16 + k) * SP + n2];
        }
    };
    auto r2s = [&](int buf) {
        As[buf][ac4 + 0][ar] = aR.x;
        As[buf][ac4 + 1][ar] = aR.y;
        As[buf][ac4 + 2][ar] = aR.z;
        As[buf][ac4 + 3][ar] = aR.w;
#pragma unroll
        for (int j = 0; j < 5; j++) {
            int e = tid + (j << 8);
            int k = e / SP, n2 = e % SP;
            Ws[buf][k][n2] = wR[j];
        }
    };

    g2r(0); r2s(0);
    __syncthreads();

    for (int kt = 0; kt < nk; ++kt) {
        const int buf = kt & 1;
        const bool more = (kt + 1 < nk);
        if (more) g2r(kt + 1);
#pragma unroll
        for (int k = 0; k < 16; k++) {
            float4 a4 = *(const float4*)&As[buf][k][ty << 2];
            float av[4] = {a4.x, a4.y, a4.z, a4.w};
#pragma unroll
            for (int j = 0; j < 5; j++) {
                float w = Ws[buf][k][tx * 5 + j];
#pragma unroll
                for (int i = 0; i < 4; i++)
                    acc[i][j] = fmaf(av[i], w, acc[i][j]);
            }
        }
        if (more) r2s(buf ^ 1);
        __syncthreads();
    }

#pragma unroll
    for (int i = 0; i < 4; i++) {
        const int row = bm + (ty << 2) + i;
#pragma unroll
        for (int j = 0; j < 5; j++)
            atomicAdd(&g_ssm[(size_t)row * SP + tx * 5 + j], acc[i][j]);
    }
}

// ============================================================================
// Fused selective scan + skip + gating. 64-step chunks, 8-t batched shuffles.
// ============================================================================
#define SC_T 64
__global__ __launch_bounds__(128)
void scan_kernel(const float* __restrict__ Alog, const float* __restrict__ Dp)
{
    __shared__ float s_h [2][SC_T][8];
    __shared__ float s_dt[2][SC_T][8];
    __shared__ float s_g [2][SC_T][8];
    __shared__ float s_B [2][SC_T][16];
    __shared__ float s_C [2][SC_T][16];

    const int tid  = threadIdx.x;
    const int lane = tid & 31;
    const int w    = tid >> 5;
    const int n    = lane & 15;
    const int half = lane >> 4;
    const int dl   = (w << 1) + half;
    const int blk  = blockIdx.x;
    const int b    = blk / (DIn / 8);
    const int d0   = (blk % (DIn / 8)) << 3;
    const int d    = d0 + dl;
    const int bL   = b * Ln;

    const float A_dn = -__expf(Alog[d * Nn + n]);
    const float Dv   = Dp[d];
    float state = 0.f;

    float rh[4], rdt[4], rg[4], rB[8], rC[8];

    auto do_load = [&](int c) {
        int t0 = c * SC_T;
#pragma unroll
        for (int j = 0; j < 4; j++) {
            int e = tid + (j << 7);
            int t = e >> 3, dd = e & 7;
            int row = bL + t0 + t;
            rh[j]  = g_h [(size_t)row * DIn + d0 + dd];
            rdt[j] = g_dt[(size_t)row * DIn + d0 + dd];
            rg[j]  = g_proj[(size_t)row * (2 * DIn) + DIn + d0 + dd];
        }
#pragma unroll
        for (int j = 0; j < 8; j++) {
            int e = tid + (j << 7);
            int t = e >> 4, nn = e & 15;
            int row = bL + t0 + t;
            rB[j] = g_ssm[(size_t)row * SP + Rn + nn];
            rC[j] = g_ssm[(size_t)row * SP + Rn + Nn + nn];
        }
    };
    auto do_store = [&](int buf) {
#pragma unroll
        for (int j = 0; j < 4; j++) {
            int e = tid + (j << 7);
            int t = e >> 3, dd = e & 7;
            s_h [buf][t][dd] = rh[j];
            s_dt[buf][t][dd] = rdt[j];
            s_g [buf][t][dd] = rg[j];
        }
#pragma unroll
        for (int j = 0; j < 8; j++) {
            int e = tid + (j << 7);
            int t = e >> 4, nn = e & 15;
            s_B[buf][t][nn] = rB[j];
            s_C[buf][t][nn] = rC[j];
        }
    };

    do_load(0);
    do_store(0);
    __syncthreads();

    const int NC = Ln / SC_T;   // 32 chunks
    for (int c = 0; c < NC; c++) {
        const int buf = c & 1;
        if (c + 1 < NC) do_load(c + 1);
        const int t0 = c * SC_T;
#pragma unroll
        for (int tb = 0; tb < SC_T; tb += 8) {
            float p[8], hs[8];
#pragma unroll
            for (int tt = 0; tt < 8; tt++) {
                const int t = tb + tt;
                float dtv = s_dt[buf][t][dl];
                float hv  = s_h [buf][t][dl];
                float Bv  = s_B [buf][t][n];
                float Cv  = s_C [buf][t][n];
                float dA  = __expf(A_dn * dtv);
                state = fmaf(dA, state, Bv * hv);
                p[tt]  = state * Cv;
                hs[tt] = hv;
            }
#pragma unroll
            for (int st = 8; st >= 1; st >>= 1)
#pragma unroll
                for (int tt = 0; tt < 8; tt++)
                    p[tt] += __shfl_xor_sync(0xffffffffu, p[tt], st);
            if (n == 0) {
#pragma unroll
                for (int tt = 0; tt < 8; tt++) {
                    const int t = tb + tt;
                    float gv = s_g[buf][t][dl];
                    float yv = (p[tt] + hs[tt] * Dv) * gv * sigmoidf_(gv);
                    g_y[(size_t)(bL + t0 + t) * DIn + d] = roundtf(yv);
                }
            }
        }
        if (c + 1 < NC) do_store(buf ^ 1);
        __syncthreads();
    }
}

// ============================================================================
extern "C" void kernel_launch(void* const* d_in, const int* in_sizes, int n_in,
                              void* d_out, int out_size)
{
    const float* x          = (const float*)d_in[0];
    const float* in_proj_w  = (const float*)d_in[1];
    const float* conv_w     = (const float*)d_in[2];
    const float* conv_b     = (const float*)d_in[3];
    const float* x_proj_w   = (const float*)d_in[4];
    const float* dt_proj_w  = (const float*)d_in[5];
    const float* dt_proj_b  = (const float*)d_in[6];
    const float* out_proj_w = (const float*)d_in[7];
    const float* A_log      = (const float*)d_in[8];
    const float* D_param    = (const float*)d_in[9];
    float* out = (float*)d_out;

    float *proj, *h, *dtraw, *dt, *y, *xr, *w1t, *w2t, *w3t;
    cudaGetSymbolAddress((void**)&proj,  g_proj);
    cudaGetSymbolAddress((void**)&h,     g_h);
    cudaGetSymbolAddress((void**)&dtraw, g_dtraw);
    cudaGetSymbolAddress((void**)&dt,    g_dt);
    cudaGetSymbolAddress((void**)&y,     g_y);
    cudaGetSymbolAddress((void**)&xr,    g_xr);
    cudaGetSymbolAddress((void**)&w1t,   g_w1);
    cudaGetSymbolAddress((void**)&w2t,   g_w2);
    cudaGetSymbolAddress((void**)&w3t,   g_w3);

    cudaFuncSetAttribute(tgemm<0>, cudaFuncAttributeMaxDynamicSharedMemorySize, TG_SMEM);
    cudaFuncSetAttribute(tgemm<1>, cudaFuncAttributeMaxDynamicSharedMemorySize, TG_SMEM);

    // 0) fused preprocessing (round x, transpose+round weights, zero ssm)
    fused_pre<<<NB_PRE, 256>>>(x, in_proj_w, dt_proj_w, out_proj_w);

    // 1) proj = x @ in_proj_w   [4096,3072], K=768
    tgemm<0><<<dim3((2 * DIn) / 128, BLn / 128), 256, TG_SMEM>>>(
        xr, Hn, w1t, Hn, proj, 2 * DIn, Hn, nullptr);

    // 2) depthwise causal conv + SiLU -> g_h
    conv_silu<<<(BLn * DIn / 4) / 256, 256>>>(proj, conv_w, conv_b, h);

    // 3) ssm += h @ x_proj_w   [4096,80] split-K
    gemm_xproj<<<dim3(BLn / 64, XKS), 256>>>(h, x_proj_w);
    round_dtraw<<<(BLn * Rn + 255) / 256, 256>>>();

    // 4) dt = softplus(dt_raw @ dt_proj_w + b)   [4096,1536], K=64 (zero-padded)
    tgemm<1><<<dim3(DIn / 128, BLn / 128), 256, TG_SMEM>>>(
        dtraw, RnP, w2t, RnP, dt, DIn, RnP, dt_proj_b);

    // 5) selective scan (+ skip + gating)
    scan_kernel<<<Bn * (DIn / 8), 128>>>(A_log, D_param);

    // 6) out = y @ out_proj_w   [4096,768], K=1536
    tgemm<0><<<dim3(Hn / 128, BLn / 128), 256, TG_SMEM>>>(
        y, DIn, w3t, DIn, out, Hn, DIn, nullptr);
}

// round 11
// speedup vs baseline: 1.0335x; 1.0335x over previous
#include <cuda_runtime.h>
#include <cstdint>
#include <cstddef>

#define Bn   2
#define Ln   2048
#define Hn   768
#define DIn  1536
#define Nn   16
#define Rn   48
#define RnP  64          /* dt K padded to 64 for BK=32 */
#define BLn  (Bn*Ln)     /* 4096 */
#define SP   (Rn + 2*Nn) /* 80 */

// -------- scratch (static device globals; zero-initialized at load) --------
__device__ float g_proj [(size_t)BLn * 2 * DIn];  // in_proj output (h | gate)
__device__ float g_h    [(size_t)BLn * DIn];      // conv+silu output
__device__ float g_ssm  [(size_t)BLn * SP];       // x_proj output (dt_raw|B|C)
__device__ float g_dtraw[(size_t)BLn * RnP];      // tf32 dt_raw, K-padded (cols 48..63 stay 0)
__device__ float g_dt   [(size_t)BLn * DIn];      // softplus(dt)
__device__ float g_y    [(size_t)BLn * DIn];      // scan output (tf32-rounded)
__device__ float g_xr   [(size_t)BLn * Hn];       // tf32-rounded x
__device__ float g_w1   [(size_t)Hn * 2 * DIn];   // in_proj_w^T  [3072][768], tf32
__device__ float g_w2   [(size_t)DIn * RnP];      // dt_proj_w^T  [1536][64],  tf32 (pad 0)
__device__ float g_w3   [(size_t)DIn * Hn];       // out_proj_w^T [768][1536], tf32

__device__ __forceinline__ float sigmoidf_(float x) { return 1.f / (1.f + __expf(-x)); }
__device__ __forceinline__ uint32_t f2tf(float f) {
    uint32_t u; asm("cvt.rna.tf32.f32 %0, %1;" : "=r"(u) : "f"(f)); return u;
}
__device__ __forceinline__ float roundtf(float f) { return __uint_as_float(f2tf(f)); }
__device__ __forceinline__ float softplusf_(float x) {
    return fmaxf(x, 0.f) + log1pf(__expf(-fabsf(x)));
}
__device__ __forceinline__ void cp16s(uint32_t sa, const void* g) {
    asm volatile("cp.async.cg.shared.global [%0], [%1], 16;\n" :: "r"(sa), "l"(g));
}
__device__ __forceinline__ void cp_commit() {
    asm volatile("cp.async.commit_group;\n");
}
template<int NN>
__device__ __forceinline__ void cp_wait() {
    asm volatile("cp.async.wait_group %0;\n" :: "n"(NN));
}
__device__ __forceinline__ uint32_t smem_u32(const void* p) {
    return (uint32_t)__cvta_generic_to_shared(p);
}
__device__ __forceinline__ void ldsm_x4(uint32_t& r0, uint32_t& r1, uint32_t& r2,
                                        uint32_t& r3, uint32_t a) {
    asm volatile("ldmatrix.sync.aligned.m8n8.x4.shared.b16 {%0,%1,%2,%3}, [%4];"
                 : "=r"(r0), "=r"(r1), "=r"(r2), "=r"(r3) : "r"(a));
}

// ============================================================================
// Fused preprocessing: one launch (round x | 3 transposes | zero ssm).
// ============================================================================
#define S0   ((size_t)BLn * Hn)
#define NBX  ((int)(S0 / 4 / 256))                          /* 3072 */
#define NBW1 ((2 * DIn / 32) * (Hn / 32))                    /* 2304 */
#define NBW2 ((DIn / 32) * ((Rn + 31) / 32))                 /* 96   */
#define NBW3 ((Hn / 32) * (DIn / 32))                        /* 1152 */
#define NBZ  ((int)((BLn * SP / 4 + 255) / 256))             /* 320  */
#define NB_PRE (NBX + NBW1 + NBW2 + NBW3 + NBZ)

__device__ __forceinline__ void transpose_tile(
    const float* __restrict__ src, float* __restrict__ dst,
    int R, int C, int Rstride, int bx, int by, float (*t)[33])
{
    const int tx = threadIdx.x & 31;
    const int ty = threadIdx.x >> 5;
#pragma unroll
    for (int i = 0; i < 32; i += 8) {
        int r = (by << 5) + ty + i, c = (bx << 5) + tx;
        if (r < R && c < C) t[ty + i][tx] = src[(size_t)r * C + c];
    }
    __syncthreads();
#pragma unroll
    for (int i = 0; i < 32; i += 8) {
        int r = (bx << 5) + ty + i, c = (by << 5) + tx;
        if (r < C && c < R) dst[(size_t)r * Rstride + c] = roundtf(t[tx][ty + i]);
    }
}

__global__ __launch_bounds__(256)
void fused_pre(const float* __restrict__ x,
               const float* __restrict__ in_proj_w,
               const float* __restrict__ dt_proj_w,
               const float* __restrict__ out_proj_w)
{
    __shared__ float t[32][33];
    int bid = blockIdx.x;

    if (bid < NBX) {
        size_t i = ((size_t)bid * 256 + threadIdx.x) * 4;
        float4 v = *(const float4*)(x + i);
        v.x = roundtf(v.x); v.y = roundtf(v.y); v.z = roundtf(v.z); v.w = roundtf(v.w);
        *(float4*)(g_xr + i) = v;
        return;
    }
    bid -= NBX;
    if (bid < NBW1) {
        const int nbx = 2 * DIn / 32;
        transpose_tile(in_proj_w, g_w1, Hn, 2 * DIn, Hn, bid % nbx, bid / nbx, t);
        return;
    }
    bid -= NBW1;
    if (bid < NBW2) {
        const int nbx = DIn / 32;
        transpose_tile(dt_proj_w, g_w2, Rn, DIn, RnP, bid % nbx, bid / nbx, t);
        return;
    }
    bid -= NBW2;
    if (bid < NBW3) {
        const int nbx = Hn / 32;
        transpose_tile(out_proj_w, g_w3, DIn, Hn, DIn, bid % nbx, bid / nbx, t);
        return;
    }
    bid -= NBW3;
    {
        size_t i = ((size_t)bid * 256 + threadIdx.x) * 4;
        if (i < (size_t)BLn * SP)
            *(float4*)&g_ssm[i] = make_float4(0.f, 0.f, 0.f, 0.f);
    }
}

__global__ __launch_bounds__(256)
void round_dtraw()
{
    int i = blockIdx.x * blockDim.x + threadIdx.x;   // over BLn*Rn
    if (i >= BLn * Rn) return;
    int row = i / Rn, col = i - row * Rn;
    g_dtraw[(size_t)row * RnP + col] = roundtf(g_ssm[(size_t)row * SP + col]);
}

// ============================================================================
// TF32 mma.sync GEMM: 128x128 CTA, 8 warps of 64x32, BK=32, 3-stage cp.async,
// ldmatrix x4 for both A and B.  C[M,N] = A[M,K](lda) @ Bt[N,K](ldb)^T.
// A,Bt pre-rounded tf32. EPI==1: C = softplus(C + bias[n]).
// ============================================================================
#define TG_STAGES 3
#define TG_TSZ (128 * 36)
#define TG_STG (2 * TG_TSZ)
#define TG_SMEM (TG_STAGES * TG_STG * 4)   /* 110592 bytes */

template<int EPI>
__global__ __launch_bounds__(256, 2)
void tgemm(const float* __restrict__ A, int lda,
           const float* __restrict__ Bt, int ldb,
           float* __restrict__ C, int N, int K,
           const float* __restrict__ bias)
{
    extern __shared__ float smem[];

    const int tid  = threadIdx.x;
    const int lane = tid & 31;
    const int warp = tid >> 5;
    const int wm   = warp >> 2;
    const int wn   = warp & 3;
    const int m0   = wm * 64;
    const int n0   = wn * 32;
    const int g    = lane >> 2;
    const int c    = lane & 3;

    const int bm = blockIdx.y << 7;
    const int bn = blockIdx.x << 7;

    const uint32_t smem0 = smem_u32(smem);

    uint32_t sOffA[4];
    const float* ApA[4];
    const float* BpA[4];
#pragma unroll
    for (int i = 0; i < 4; i++) {
        const int ch  = tid + (i << 8);
        const int row = ch >> 3;
        const int k4  = (ch & 7) << 2;
        sOffA[i] = (uint32_t)(row * 36 + k4) * 4;
        ApA[i] = A  + (size_t)(bm + row) * lda + k4;
        BpA[i] = Bt + (size_t)(bn + row) * ldb + k4;
    }

    const int arow = m0 + (lane & 7) + ((lane & 8) ? 8 : 0);
    const int acol = (lane & 16) ? 4 : 0;
    const uint32_t aBase = (uint32_t)(arow * 36 + acol) * 4;
    const int brow = n0 + (lane & 7) + ((lane & 16) ? 8 : 0);
    const int bcol = (lane & 8) ? 4 : 0;
    const uint32_t bBase = (uint32_t)(brow * 36 + bcol) * 4;

    float acc[4][4][4];
#pragma unroll
    for (int i = 0; i < 4; i++)
#pragma unroll
        for (int j = 0; j < 4; j++)
#pragma unroll
            for (int q = 0; q < 4; q++) acc[i][j][q] = 0.f;

    const int nk = K >> 5;

    auto load_stage = [&](int kt, int s) {
        const uint32_t stA = smem0 + (uint32_t)(s * TG_STG) * 4;
        const uint32_t stB = stA + TG_TSZ * 4;
        const int k0 = kt << 5;
#pragma unroll
        for (int i = 0; i < 4; i++) {
            cp16s(stA + sOffA[i], ApA[i] + k0);
            cp16s(stB + sOffA[i], BpA[i] + k0);
        }
    };
    auto compute = [&](int s) {
        const uint32_t stA = smem0 + (uint32_t)(s * TG_STG) * 4;
        const uint32_t stB = stA + TG_TSZ * 4;
#pragma unroll
        for (int ks = 0; ks < 4; ks++) {
            const uint32_t kb = (uint32_t)(ks << 3) * 4;
            uint32_t af[4][4], bf[4][2];
#pragma unroll
            for (int i = 0; i < 4; i++)
                ldsm_x4(af[i][0], af[i][1], af[i][2], af[i][3],
                        stA + aBase + (uint32_t)(i * 16 * 36) * 4 + kb);
#pragma unroll
            for (int jj = 0; jj < 2; jj++)
                ldsm_x4(bf[2 * jj][0], bf[2 * jj][1], bf[2 * jj + 1][0], bf[2 * jj + 1][1],
                        stB + bBase + (uint32_t)(jj * 16 * 36) * 4 + kb);
#pragma unroll
            for (int i = 0; i < 4; i++)
#pragma unroll
                for (int j = 0; j < 4; j++)
                    asm volatile(
                        "mma.sync.aligned.m16n8k8.row.col.f32.tf32.tf32.f32 "
                        "{%0,%1,%2,%3}, {%4,%5,%6,%7}, {%8,%9}, {%0,%1,%2,%3};\n"
                        : "+f"(acc[i][j][0]), "+f"(acc[i][j][1]),
                          "+f"(acc[i][j][2]), "+f"(acc[i][j][3])
                        : "r"(af[i][0]), "r"(af[i][1]), "r"(af[i][2]), "r"(af[i][3]),
                          "r"(bf[j][0]), "r"(bf[j][1]));
        }
    };

#pragma unroll
    for (int s = 0; s < TG_STAGES - 1; s++) {
        if (s < nk) load_stage(s, s);
        cp_commit();
    }
    for (int kt = 0; kt < nk; ++kt) {
        cp_wait<TG_STAGES - 2>();
        __syncthreads();
        const int nxt = kt + TG_STAGES - 1;
        if (nxt < nk) load_stage(nxt, nxt % TG_STAGES);
        cp_commit();
        compute(kt % TG_STAGES);
    }

#pragma unroll
    for (int i = 0; i < 4; i++) {
        const int r0 = bm + m0 + i * 16 + g;
#pragma unroll
        for (int j = 0; j < 4; j++) {
            const int col = bn + n0 + j * 8 + 2 * c;
            float v00 = acc[i][j][0], v01 = acc[i][j][1];
            float v10 = acc[i][j][2], v11 = acc[i][j][3];
            if (EPI == 1) {
                const float b0v = bias[col], b1v = bias[col + 1];
                v00 = softplusf_(v00 + b0v);
                v01 = softplusf_(v01 + b1v);
                v10 = softplusf_(v10 + b0v);
                v11 = softplusf_(v11 + b1v);
            }
            *(float2*)&C[(size_t)r0 * N + col]       = make_float2(v00, v01);
            *(float2*)&C[(size_t)(r0 + 8) * N + col] = make_float2(v10, v11);
        }
    }
}

// ============================================================================
// Depthwise causal conv (K=4) + bias + SiLU, 4 channels/thread.
// ============================================================================
__global__ __launch_bounds__(256)
void conv_silu(const float* __restrict__ proj,
               const float* __restrict__ cw,
               const float* __restrict__ cb,
               float* __restrict__ h)
{
    int idx = blockIdx.x * blockDim.x + threadIdx.x;
    int d4 = (idx % (DIn / 4)) << 2;
    int bt = idx / (DIn / 4);
    int t  = bt % Ln;

    const float* p = proj + (size_t)bt * (2 * DIn) + d4;
    const int s = 2 * DIn;
    float4 z  = make_float4(0.f, 0.f, 0.f, 0.f);
    float4 x0 = *(const float4*)p;
    float4 x1 = (t >= 1) ? *(const float4*)(p - s)     : z;
    float4 x2 = (t >= 2) ? *(const float4*)(p - 2 * s) : z;
    float4 x3 = (t >= 3) ? *(const float4*)(p - 3 * s) : z;
    float4 cbv = *(const float4*)(cb + d4);
    float4 w0 = *(const float4*)(cw + (d4 + 0) * 4);
    float4 w1 = *(const float4*)(cw + (d4 + 1) * 4);
    float4 w2 = *(const float4*)(cw + (d4 + 2) * 4);
    float4 w3 = *(const float4*)(cw + (d4 + 3) * 4);

    float4 o;
    o.x = fmaf(x3.x, w0.x, fmaf(x2.x, w0.y, fmaf(x1.x, w0.z, fmaf(x0.x, w0.w, cbv.x))));
    o.y = fmaf(x3.y, w1.x, fmaf(x2.y, w1.y, fmaf(x1.y, w1.z, fmaf(x0.y, w1.w, cbv.y))));
    o.z = fmaf(x3.z, w2.x, fmaf(x2.z, w2.y, fmaf(x1.z, w2.z, fmaf(x0.z, w2.w, cbv.z))));
    o.w = fmaf(x3.w, w3.x, fmaf(x2.w, w3.y, fmaf(x1.w, w3.z, fmaf(x0.w, w3.w, cbv.w))));
    o.x = o.x * sigmoidf_(o.x);
    o.y = o.y * sigmoidf_(o.y);
    o.z = o.z * sigmoidf_(o.z);
    o.w = o.w * sigmoidf_(o.w);
    *(float4*)(h + (size_t)bt * DIn + d4) = o;
}

// ============================================================================
// x_proj GEMM, split-K=8: ssm += h @ x_proj_w.  512 blocks for MLP.
// ============================================================================
#define XKS 8
#define XKC (DIn / XKS)   /* 192 */
__global__ __launch_bounds__(256)
void gemm_xproj(const float* __restrict__ A,
                const float* __restrict__ W)
{
    __shared__ float As[2][16][68];
    __shared__ float Ws[2][16][SP];

    const int tid = threadIdx.x;
    const int bm  = blockIdx.x << 6;
    const int k0  = blockIdx.y * XKC;
    const int tx  = tid & 15;
    const int ty  = tid >> 4;
    const int ar  = tid >> 2;
    const int ac4 = (tid & 3) << 2;

    float acc[4][5];
#pragma unroll
    for (int i = 0; i < 4; i++)
#pragma unroll
        for (int j = 0; j < 5; j++) acc[i][j] = 0.f;

    const float* Ap = A + (size_t)(bm + ar) * DIn + k0 + ac4;
    const int nk = XKC / 16;   // 12

    float4 aR; float wR[5];
    auto g2r = [&](int kt) {
        aR = *(const float4*)(Ap + kt * 16);
#pragma unroll
        for (int j = 0; j < 5; j++) {
            int e = tid + (j << 8);
            int k = e / SP, n2 = e % SP;
            wR[j] = W[(size_t)(k0 + kt * 16 + k) * SP + n2];
        }
    };
    auto r2s = [&](int buf) {
        As[buf][ac4 + 0][ar] = aR.x;
        As[buf][ac4 + 1][ar] = aR.y;
        As[buf][ac4 + 2][ar] = aR.z;
        As[buf][ac4 + 3][ar] = aR.w;
#pragma unroll
        for (int j = 0; j < 5; j++) {
            int e = tid + (j << 8);
            int k = e / SP, n2 = e % SP;
            Ws[buf][k][n2] = wR[j];
        }
    };

    g2r(0); r2s(0);
    __syncthreads();

    for (int kt = 0; kt < nk; ++kt) {
        const int buf = kt & 1;
        const bool more = (kt + 1 < nk);
        if (more) g2r(kt + 1);
#pragma unroll
        for (int k = 0; k < 16; k++) {
            float4 a4 = *(const float4*)&As[buf][k][ty << 2];
            float av[4] = {a4.x, a4.y, a4.z, a4.w};
#pragma unroll
            for (int j = 0; j < 5; j++) {
                float w = Ws[buf][k][tx * 5 + j];
#pragma unroll
                for (int i = 0; i < 4; i++)
                    acc[i][j] = fmaf(av[i], w, acc[i][j]);
            }
        }
        if (more) r2s(buf ^ 1);
        __syncthreads();
    }

#pragma unroll
    for (int i = 0; i < 4; i++) {
        const int row = bm + (ty << 2) + i;
#pragma unroll
        for (int j = 0; j < 5; j++)
            atomicAdd(&g_ssm[(size_t)row * SP + tx * 5 + j], acc[i][j]);
    }
}

// ============================================================================
// Fused selective scan + skip + gating. 64-step chunks, 8-t batched shuffles.
// ============================================================================
#define SC_T 64
__global__ __launch_bounds__(128)
void scan_kernel(const float* __restrict__ Alog, const float* __restrict__ Dp)
{
    __shared__ float s_h [2][SC_T][8];
    __shared__ float s_dt[2][SC_T][8];
    __shared__ float s_g [2][SC_T][8];
    __shared__ float s_B [2][SC_T][16];
    __shared__ float s_C [2][SC_T][16];

    const int tid  = threadIdx.x;
    const int lane = tid & 31;
    const int w    = tid >> 5;
    const int n    = lane & 15;
    const int half = lane >> 4;
    const int dl   = (w << 1) + half;
    const int blk  = blockIdx.x;
    const int b    = blk / (DIn / 8);
    const int d0   = (blk % (DIn / 8)) << 3;
    const int d    = d0 + dl;
    const int bL   = b * Ln;

    const float A_dn = -__expf(Alog[d * Nn + n]);
    const float Dv   = Dp[d];
    float state = 0.f;

    float rh[4], rdt[4], rg[4], rB[8], rC[8];

    auto do_load = [&](int c) {
        int t0 = c * SC_T;
#pragma unroll
        for (int j = 0; j < 4; j++) {
            int e = tid + (j << 7);
            int t = e >> 3, dd = e & 7;
            int row = bL + t0 + t;
            rh[j]  = g_h [(size_t)row * DIn + d0 + dd];
            rdt[j] = g_dt[(size_t)row * DIn + d0 + dd];
            rg[j]  = g_proj[(size_t)row * (2 * DIn) + DIn + d0 + dd];
        }
#pragma unroll
        for (int j = 0; j < 8; j++) {
            int e = tid + (j << 7);
            int t = e >> 4, nn = e & 15;
            int row = bL + t0 + t;
            rB[j] = g_ssm[(size_t)row * SP + Rn + nn];
            rC[j] = g_ssm[(size_t)row * SP + Rn + Nn + nn];
        }
    };
    auto do_store = [&](int buf) {
#pragma unroll
        for (int j = 0; j < 4; j++) {
            int e = tid + (j << 7);
            int t = e >> 3, dd = e & 7;
            s_h [buf][t][dd] = rh[j];
            s_dt[buf][t][dd] = rdt[j];
            s_g [buf][t][dd] = rg[j];
        }
#pragma unroll
        for (int j = 0; j < 8; j++) {
            int e = tid + (j << 7);
            int t = e >> 4, nn = e & 15;
            s_B[buf][t][nn] = rB[j];
            s_C[buf][t][nn] = rC[j];
        }
    };

    do_load(0);
    do_store(0);
    __syncthreads();

    const int NC = Ln / SC_T;   // 32 chunks
    for (int c = 0; c < NC; c++) {
        const int buf = c & 1;
        if (c + 1 < NC) do_load(c + 1);
        const int t0 = c * SC_T;
#pragma unroll
        for (int tb = 0; tb < SC_T; tb += 8) {
            float p[8], hs[8];
#pragma unroll
            for (int tt = 0; tt < 8; tt++) {
                const int t = tb + tt;
                float dtv = s_dt[buf][t][dl];
                float hv  = s_h [buf][t][dl];
                float Bv  = s_B [buf][t][n];
                float Cv  = s_C [buf][t][n];
                float dA  = __expf(A_dn * dtv);
                state = fmaf(dA, state, Bv * hv);
                p[tt]  = state * Cv;
                hs[tt] = hv;
            }
#pragma unroll
            for (int st = 8; st >= 1; st >>= 1)
#pragma unroll
                for (int tt = 0; tt < 8; tt++)
                    p[tt] += __shfl_xor_sync(0xffffffffu, p[tt], st);
            if (n == 0) {
#pragma unroll
                for (int tt = 0; tt < 8; tt++) {
                    const int t = tb + tt;
                    float gv = s_g[buf][t][dl];
                    float yv = (p[tt] + hs[tt] * Dv) * gv * sigmoidf_(gv);
                    g_y[(size_t)(bL + t0 + t) * DIn + d] = roundtf(yv);
                }
            }
        }
        if (c + 1 < NC) do_store(buf ^ 1);
        __syncthreads();
    }
}

// ============================================================================
extern "C" void kernel_launch(void* const* d_in, const int* in_sizes, int n_in,
                              void* d_out, int out_size)
{
    const float* x          = (const float*)d_in[0];
    const float* in_proj_w  = (const float*)d_in[1];
    const float* conv_w     = (const float*)d_in[2];
    const float* conv_b     = (const float*)d_in[3];
    const float* x_proj_w   = (const float*)d_in[4];
    const float* dt_proj_w  = (const float*)d_in[5];
    const float* dt_proj_b  = (const float*)d_in[6];
    const float* out_proj_w = (const float*)d_in[7];
    const float* A_log      = (const float*)d_in[8];
    const float* D_param    = (const float*)d_in[9];
    float* out = (float*)d_out;

    float *proj, *h, *dtraw, *dt, *y, *xr, *w1t, *w2t, *w3t;
    cudaGetSymbolAddress((void**)&proj,  g_proj);
    cudaGetSymbolAddress((void**)&h,     g_h);
    cudaGetSymbolAddress((void**)&dtraw, g_dtraw);
    cudaGetSymbolAddress((void**)&dt,    g_dt);
    cudaGetSymbolAddress((void**)&y,     g_y);
    cudaGetSymbolAddress((void**)&xr,    g_xr);
    cudaGetSymbolAddress((void**)&w1t,   g_w1);
    cudaGetSymbolAddress((void**)&w2t,   g_w2);
    cudaGetSymbolAddress((void**)&w3t,   g_w3);

    cudaFuncSetAttribute(tgemm<0>, cudaFuncAttributeMaxDynamicSharedMemorySize, TG_SMEM);
    cudaFuncSetAttribute(tgemm<1>, cudaFuncAttributeMaxDynamicSharedMemorySize, TG_SMEM);

    // 0) fused preprocessing (round x, transpose+round weights, zero ssm)
    fused_pre<<<NB_PRE, 256>>>(x, in_proj_w, dt_proj_w, out_proj_w);

    // 1) proj = x @ in_proj_w   [4096,3072], K=768
    tgemm<0><<<dim3((2 * DIn) / 128, BLn / 128), 256, TG_SMEM>>>(
        xr, Hn, w1t, Hn, proj, 2 * DIn, Hn, nullptr);

    // 2) depthwise causal conv + SiLU -> g_h
    conv_silu<<<(BLn * DIn / 4) / 256, 256>>>(proj, conv_w, conv_b, h);

    // 3) ssm += h @ x_proj_w   [4096,80] split-K=8
    gemm_xproj<<<dim3(BLn / 64, XKS), 256>>>(h, x_proj_w);
    round_dtraw<<<(BLn * Rn + 255) / 256, 256>>>();

    // 4) dt = softplus(dt_raw @ dt_proj_w + b)   [4096,1536], K=64 (zero-padded)
    tgemm<1><<<dim3(DIn / 128, BLn / 128), 256, TG_SMEM>>>(
        dtraw, RnP, w2t, RnP, dt, DIn, RnP, dt_proj_b);

    // 5) selective scan (+ skip + gating)
    scan_kernel<<<Bn * (DIn / 8), 128>>>(A_log, D_param);

    // 6) out = y @ out_proj_w   [4096,768], K=1536
    tgemm<0><<<dim3(Hn / 128, BLn / 128), 256, TG_SMEM>>>(
        y, DIn, w3t, DIn, out, Hn, DIn, nullptr);
}

// round 13
// speedup vs baseline: 1.0982x; 1.0626x over previous
#include <cuda_runtime.h>
#include <cstdint>
#include <cstddef>

#define Bn   2
#define Ln   2048
#define Hn   768
#define DIn  1536
#define Nn   16
#define Rn   48
#define RnP  64          /* dt K padded to 64 for BK=32 */
#define BLn  (Bn*Ln)     /* 4096 */
#define SP   (Rn + 2*Nn) /* 80 */
#define XNP  128         /* x_proj N padded 80 -> 128 */
#define XKS  8           /* x_proj K splits */
#define XKC  (DIn / XKS) /* 192 */

// -------- scratch (static device globals; zero-initialized at load) --------
__device__ float g_proj [(size_t)BLn * 2 * DIn];  // in_proj output (h | gate)
__device__ float g_h    [(size_t)BLn * DIn];      // conv+silu output
__device__ float g_ssm  [(size_t)BLn * SP];       // x_proj output (dt_raw|B|C)
__device__ float g_part [(size_t)XKS * BLn * XNP];// x_proj split-K partials
__device__ float g_dtraw[(size_t)BLn * RnP];      // tf32 dt_raw, K-padded (cols 48..63 stay 0)
__device__ float g_dt   [(size_t)BLn * DIn];      // softplus(dt)
__device__ float g_y    [(size_t)BLn * DIn];      // scan output (tf32-rounded)
__device__ float g_xr   [(size_t)BLn * Hn];       // tf32-rounded x
__device__ float g_w1   [(size_t)Hn * 2 * DIn];   // in_proj_w^T  [3072][768], tf32
__device__ float g_w2   [(size_t)DIn * RnP];      // dt_proj_w^T  [1536][64],  tf32 (pad 0)
__device__ float g_w3   [(size_t)DIn * Hn];       // out_proj_w^T [768][1536], tf32
__device__ float g_wx   [(size_t)XNP * DIn];      // x_proj_w^T   [128][1536], tf32 (rows 80+ zero)

__device__ __forceinline__ float sigmoidf_(float x) { return 1.f / (1.f + __expf(-x)); }
__device__ __forceinline__ uint32_t f2tf(float f) {
    uint32_t u; asm("cvt.rna.tf32.f32 %0, %1;" : "=r"(u) : "f"(f)); return u;
}
__device__ __forceinline__ float roundtf(float f) { return __uint_as_float(f2tf(f)); }
__device__ __forceinline__ float softplusf_(float x) {
    return fmaxf(x, 0.f) + log1pf(__expf(-fabsf(x)));
}
__device__ __forceinline__ void cp16s(uint32_t sa, const void* g) {
    asm volatile("cp.async.cg.shared.global [%0], [%1], 16;\n" :: "r"(sa), "l"(g));
}
__device__ __forceinline__ void cp_commit() {
    asm volatile("cp.async.commit_group;\n");
}
template<int NN>
__device__ __forceinline__ void cp_wait() {
    asm volatile("cp.async.wait_group %0;\n" :: "n"(NN));
}
__device__ __forceinline__ uint32_t smem_u32(const void* p) {
    return (uint32_t)__cvta_generic_to_shared(p);
}
__device__ __forceinline__ void ldsm_x4(uint32_t& r0, uint32_t& r1, uint32_t& r2,
                                        uint32_t& r3, uint32_t a) {
    asm volatile("ldmatrix.sync.aligned.m8n8.x4.shared.b16 {%0,%1,%2,%3}, [%4];"
                 : "=r"(r0), "=r"(r1), "=r"(r2), "=r"(r3) : "r"(a));
}

// ============================================================================
// Fused preprocessing: one launch (round x | 4 weight transposes).
// ============================================================================
#define S0   ((size_t)BLn * Hn)
#define NBX  ((int)(S0 / 4 / 256))                          /* 3072 */
#define NBW1 ((2 * DIn / 32) * (Hn / 32))                    /* 2304 */
#define NBW2 ((DIn / 32) * ((Rn + 31) / 32))                 /* 96   */
#define NBW3 ((Hn / 32) * (DIn / 32))                        /* 1152 */
#define NBW4 (((SP + 31) / 32) * (DIn / 32))                 /* 144  */
#define NB_PRE (NBX + NBW1 + NBW2 + NBW3 + NBW4)

__device__ __forceinline__ void transpose_tile(
    const float* __restrict__ src, float* __restrict__ dst,
    int R, int C, int Rstride, int bx, int by, float (*t)[33])
{
    const int tx = threadIdx.x & 31;
    const int ty = threadIdx.x >> 5;
#pragma unroll
    for (int i = 0; i < 32; i += 8) {
        int r = (by << 5) + ty + i, c = (bx << 5) + tx;
        if (r < R && c < C) t[ty + i][tx] = src[(size_t)r * C + c];
    }
    __syncthreads();
#pragma unroll
    for (int i = 0; i < 32; i += 8) {
        int r = (bx << 5) + ty + i, c = (by << 5) + tx;
        if (r < C && c < R) dst[(size_t)r * Rstride + c] = roundtf(t[tx][ty + i]);
    }
}

__global__ __launch_bounds__(256)
void fused_pre(const float* __restrict__ x,
               const float* __restrict__ in_proj_w,
               const float* __restrict__ dt_proj_w,
               const float* __restrict__ out_proj_w,
               const float* __restrict__ x_proj_w)
{
    __shared__ float t[32][33];
    int bid = blockIdx.x;

    if (bid < NBX) {
        size_t i = ((size_t)bid * 256 + threadIdx.x) * 4;
        float4 v = *(const float4*)(x + i);
        v.x = roundtf(v.x); v.y = roundtf(v.y); v.z = roundtf(v.z); v.w = roundtf(v.w);
        *(float4*)(g_xr + i) = v;
        return;
    }
    bid -= NBX;
    if (bid < NBW1) {
        const int nbx = 2 * DIn / 32;   // C/32
        transpose_tile(in_proj_w, g_w1, Hn, 2 * DIn, Hn, bid % nbx, bid / nbx, t);
        return;
    }
    bid -= NBW1;
    if (bid < NBW2) {
        const int nbx = DIn / 32;       // C/32
        transpose_tile(dt_proj_w, g_w2, Rn, DIn, RnP, bid % nbx, bid / nbx, t);
        return;
    }
    bid -= NBW2;
    if (bid < NBW3) {
        const int nbx = Hn / 32;        // C/32
        transpose_tile(out_proj_w, g_w3, DIn, Hn, DIn, bid % nbx, bid / nbx, t);
        return;
    }
    bid -= NBW3;
    {
        const int nbx = (SP + 31) / 32; // C/32 = 3  (FIXED: was DIn/32)
        transpose_tile(x_proj_w, g_wx, DIn, SP, DIn, bid % nbx, bid / nbx, t);
    }
}

// ============================================================================
// xreduce: sum 8 split-K partials -> g_ssm; rounded dt_raw cols -> g_dtraw.
// ============================================================================
__global__ __launch_bounds__(256)
void xreduce()
{
    int i = blockIdx.x * blockDim.x + threadIdx.x;   // over BLn*SP
    if (i >= BLn * SP) return;
    int row = i / SP, col = i - row * SP;
    float s = 0.f;
#pragma unroll
    for (int z = 0; z < XKS; z++)
        s += g_part[(size_t)z * BLn * XNP + (size_t)row * XNP + col];
    g_ssm[i] = s;
    if (col < Rn) g_dtraw[(size_t)row * RnP + col] = roundtf(s);
}

// ============================================================================
// TF32 mma.sync GEMM: 128x128 CTA, 8 warps of 64x32, BK=32, 3-stage cp.async,
// ldmatrix x4 for A and B.  C[M,N] = A[M,K](lda) @ Bt[N,K](ldb)^T.
// blockIdx.z = K-split index: A,Bt advance by z*K along k; C by z*csplit.
// EPI==1: C = softplus(C + bias[n]).
// ============================================================================
#define TG_STAGES 3
#define TG_TSZ (128 * 36)
#define TG_STG (2 * TG_TSZ)
#define TG_SMEM (TG_STAGES * TG_STG * 4)   /* 110592 bytes */

template<int EPI>
__global__ __launch_bounds__(256, 2)
void tgemm(const float* __restrict__ A, int lda,
           const float* __restrict__ Bt, int ldb,
           float* __restrict__ C, int N, int K,
           const float* __restrict__ bias, size_t csplit)
{
    extern __shared__ float smem[];

    const int tid  = threadIdx.x;
    const int lane = tid & 31;
    const int warp = tid >> 5;
    const int wm   = warp >> 2;
    const int wn   = warp & 3;
    const int m0   = wm * 64;
    const int n0   = wn * 32;
    const int g    = lane >> 2;
    const int c    = lane & 3;

    const int bm = blockIdx.y << 7;
    const int bn = blockIdx.x << 7;
    const int kz = blockIdx.z;
    A  += (size_t)kz * K;
    Bt += (size_t)kz * K;
    C  += (size_t)kz * csplit;

    const uint32_t smem0 = smem_u32(smem);

    uint32_t sOffA[4];
    const float* ApA[4];
    const float* BpA[4];
#pragma unroll
    for (int i = 0; i < 4; i++) {
        const int ch  = tid + (i << 8);
        const int row = ch >> 3;
        const int k4  = (ch & 7) << 2;
        sOffA[i] = (uint32_t)(row * 36 + k4) * 4;
        ApA[i] = A  + (size_t)(bm + row) * lda + k4;
        BpA[i] = Bt + (size_t)(bn + row) * ldb + k4;
    }

    const int arow = m0 + (lane & 7) + ((lane & 8) ? 8 : 0);
    const int acol = (lane & 16) ? 4 : 0;
    const uint32_t aBase = (uint32_t)(arow * 36 + acol) * 4;
    const int brow = n0 + (lane & 7) + ((lane & 16) ? 8 : 0);
    const int bcol = (lane & 8) ? 4 : 0;
    const uint32_t bBase = (uint32_t)(brow * 36 + bcol) * 4;

    float acc[4][4][4];
#pragma unroll
    for (int i = 0; i < 4; i++)
#pragma unroll
        for (int j = 0; j < 4; j++)
#pragma unroll
            for (int q = 0; q < 4; q++) acc[i][j][q] = 0.f;

    const int nk = K >> 5;

    auto load_stage = [&](int kt, int s) {
        const uint32_t stA = smem0 + (uint32_t)(s * TG_STG) * 4;
        const uint32_t stB = stA + TG_TSZ * 4;
        const int k0 = kt << 5;
#pragma unroll
        for (int i = 0; i < 4; i++) {
            cp16s(stA + sOffA[i], ApA[i] + k0);
            cp16s(stB + sOffA[i], BpA[i] + k0);
        }
    };
    auto compute = [&](int s) {
        const uint32_t stA = smem0 + (uint32_t)(s * TG_STG) * 4;
        const uint32_t stB = stA + TG_TSZ * 4;
#pragma unroll
        for (int ks = 0; ks < 4; ks++) {
            const uint32_t kb = (uint32_t)(ks << 3) * 4;
            uint32_t af[4][4], bf[4][2];
#pragma unroll
            for (int i = 0; i < 4; i++)
                ldsm_x4(af[i][0], af[i][1], af[i][2], af[i][3],
                        stA + aBase + (uint32_t)(i * 16 * 36) * 4 + kb);
#pragma unroll
            for (int jj = 0; jj < 2; jj++)
                ldsm_x4(bf[2 * jj][0], bf[2 * jj][1], bf[2 * jj + 1][0], bf[2 * jj + 1][1],
                        stB + bBase + (uint32_t)(jj * 16 * 36) * 4 + kb);
#pragma unroll
            for (int i = 0; i < 4; i++)
#pragma unroll
                for (int j = 0; j < 4; j++)
                    asm volatile(
                        "mma.sync.aligned.m16n8k8.row.col.f32.tf32.tf32.f32 "
                        "{%0,%1,%2,%3}, {%4,%5,%6,%7}, {%8,%9}, {%0,%1,%2,%3};\n"
                        : "+f"(acc[i][j][0]), "+f"(acc[i][j][1]),
                          "+f"(acc[i][j][2]), "+f"(acc[i][j][3])
                        : "r"(af[i][0]), "r"(af[i][1]), "r"(af[i][2]), "r"(af[i][3]),
                          "r"(bf[j][0]), "r"(bf[j][1]));
        }
    };

#pragma unroll
    for (int s = 0; s < TG_STAGES - 1; s++) {
        if (s < nk) load_stage(s, s);
        cp_commit();
    }
    for (int kt = 0; kt < nk; ++kt) {
        cp_wait<TG_STAGES - 2>();
        __syncthreads();
        const int nxt = kt + TG_STAGES - 1;
        if (nxt < nk) load_stage(nxt, nxt % TG_STAGES);
        cp_commit();
        compute(kt % TG_STAGES);
    }

#pragma unroll
    for (int i = 0; i < 4; i++) {
        const int r0 = bm + m0 + i * 16 + g;
#pragma unroll
        for (int j = 0; j < 4; j++) {
            const int col = bn + n0 + j * 8 + 2 * c;
            float v00 = acc[i][j][0], v01 = acc[i][j][1];
            float v10 = acc[i][j][2], v11 = acc[i][j][3];
            if (EPI == 1) {
                const float b0v = bias[col], b1v = bias[col + 1];
                v00 = softplusf_(v00 + b0v);
                v01 = softplusf_(v01 + b1v);
                v10 = softplusf_(v10 + b0v);
                v11 = softplusf_(v11 + b1v);
            }
            *(float2*)&C[(size_t)r0 * N + col]       = make_float2(v00, v01);
            *(float2*)&C[(size_t)(r0 + 8) * N + col] = make_float2(v10, v11);
        }
    }
}

// ============================================================================
// Depthwise causal conv (K=4) + bias + SiLU. 4 channels x 4 timesteps/thread.
// ============================================================================
__global__ __launch_bounds__(256)
void conv_silu(const float* __restrict__ proj,
               const float* __restrict__ cw,
               const float* __restrict__ cb,
               float* __restrict__ h)
{
    int idx = blockIdx.x * blockDim.x + threadIdx.x;   // over (BLn/4)*(DIn/4)
    int d4  = (idx % (DIn / 4)) << 2;
    int bt4 = idx / (DIn / 4);
    int tb  = (bt4 & (Ln / 4 - 1)) << 2;                // t0 within batch
    size_t row0 = (size_t)bt4 * 4;                      // global row of t0

    const int s = 2 * DIn;
    const float* p = proj + row0 * s + d4;
    float4 z = make_float4(0.f, 0.f, 0.f, 0.f);
    float4 r[7];                                        // rows tb-3 .. tb+3
#pragma unroll
    for (int j = 0; j < 7; j++) {
        int tt = tb - 3 + j;
        r[j] = (tt >= 0) ? *(const float4*)(p + (ptrdiff_t)(j - 3) * s) : z;
    }
    float4 cbv = *(const float4*)(cb + d4);
    float4 w0 = *(const float4*)(cw + (d4 + 0) * 4);
    float4 w1 = *(const float4*)(cw + (d4 + 1) * 4);
    float4 w2 = *(const float4*)(cw + (d4 + 2) * 4);
    float4 w3 = *(const float4*)(cw + (d4 + 3) * 4);

#pragma unroll
    for (int i = 0; i < 4; i++) {
        float4 o;
        o.x = fmaf(r[i].x, w0.x, fmaf(r[i+1].x, w0.y, fmaf(r[i+2].x, w0.z, fmaf(r[i+3].x, w0.w, cbv.x))));
        o.y = fmaf(r[i].y, w1.x, fmaf(r[i+1].y, w1.y, fmaf(r[i+2].y, w1.z, fmaf(r[i+3].y, w1.w, cbv.y))));
        o.z = fmaf(r[i].z, w2.x, fmaf(r[i+1].z, w2.y, fmaf(r[i+2].z, w2.z, fmaf(r[i+3].z, w2.w, cbv.z))));
        o.w = fmaf(r[i].w, w3.x, fmaf(r[i+1].w, w3.y, fmaf(r[i+2].w, w3.z, fmaf(r[i+3].w, w3.w, cbv.w))));
        o.x = o.x * sigmoidf_(o.x);
        o.y = o.y * sigmoidf_(o.y);
        o.z = o.z * sigmoidf_(o.z);
        o.w = o.w * sigmoidf_(o.w);
        *(float4*)(h + (row0 + i) * DIn + d4) = o;
    }
}

// ============================================================================
// Fused selective scan + skip + gating. 64-step chunks, 8-t batched shuffles.
// ============================================================================
#define SC_T 64
__global__ __launch_bounds__(128)
void scan_kernel(const float* __restrict__ Alog, const float* __restrict__ Dp)
{
    __shared__ float s_h [2][SC_T][8];
    __shared__ float s_dt[2][SC_T][8];
    __shared__ float s_g [2][SC_T][8];
    __shared__ float s_B [2][SC_T][16];
    __shared__ float s_C [2][SC_T][16];

    const int tid  = threadIdx.x;
    const int lane = tid & 31;
    const int w    = tid >> 5;
    const int n    = lane & 15;
    const int half = lane >> 4;
    const int dl   = (w << 1) + half;
    const int blk  = blockIdx.x;
    const int b    = blk / (DIn / 8);
    const int d0   = (blk % (DIn / 8)) << 3;
    const int d    = d0 + dl;
    const int bL   = b * Ln;

    const float A_dn = -__expf(Alog[d * Nn + n]);
    const float Dv   = Dp[d];
    float state = 0.f;

    float rh[4], rdt[4], rg[4], rB[8], rC[8];

    auto do_load = [&](int c) {
        int t0 = c * SC_T;
#pragma unroll
        for (int j = 0; j < 4; j++) {
            int e = tid + (j << 7);
            int t = e >> 3, dd = e & 7;
            int row = bL + t0 + t;
            rh[j]  = g_h [(size_t)row * DIn + d0 + dd];
            rdt[j] = g_dt[(size_t)row * DIn + d0 + dd];
            rg[j]  = g_proj[(size_t)row * (2 * DIn) + DIn + d0 + dd];
        }
#pragma unroll
        for (int j = 0; j < 8; j++) {
            int e = tid + (j << 7);
            int t = e >> 4, nn = e & 15;
            int row = bL + t0 + t;
            rB[j] = g_ssm[(size_t)row * SP + Rn + nn];
            rC[j] = g_ssm[(size_t)row * SP + Rn + Nn + nn];
        }
    };
    auto do_store = [&](int buf) {
#pragma unroll
        for (int j = 0; j < 4; j++) {
            int e = tid + (j << 7);
            int t = e >> 3, dd = e & 7;
            s_h [buf][t][dd] = rh[j];
            s_dt[buf][t][dd] = rdt[j];
            s_g [buf][t][dd] = rg[j];
        }
#pragma unroll
        for (int j = 0; j < 8; j++) {
            int e = tid + (j << 7);
            int t = e >> 4, nn = e & 15;
            s_B[buf][t][nn] = rB[j];
            s_C[buf][t][nn] = rC[j];
        }
    };

    do_load(0);
    do_store(0);
    __syncthreads();

    const int NC = Ln / SC_T;
    for (int c = 0; c < NC; c++) {
        const int buf = c & 1;
        if (c + 1 < NC) do_load(c + 1);
        const int t0 = c * SC_T;
#pragma unroll
        for (int tb = 0; tb < SC_T; tb += 8) {
            float p[8], hs[8];
#pragma unroll
            for (int tt = 0; tt < 8; tt++) {
                const int t = tb + tt;
                float dtv = s_dt[buf][t][dl];
                float hv  = s_h [buf][t][dl];
                float Bv  = s_B [buf][t][n];
                float Cv  = s_C [buf][t][n];
                float dA  = __expf(A_dn * dtv);
                state = fmaf(dA, state, Bv * hv);
                p[tt]  = state * Cv;
                hs[tt] = hv;
            }
#pragma unroll
            for (int st = 8; st >= 1; st >>= 1)
#pragma unroll
                for (int tt = 0; tt < 8; tt++)
                    p[tt] += __shfl_xor_sync(0xffffffffu, p[tt], st);
            if (n == 0) {
#pragma unroll
                for (int tt = 0; tt < 8; tt++) {
                    const int t = tb + tt;
                    float gv = s_g[buf][t][dl];
                    float yv = (p[tt] + hs[tt] * Dv) * gv * sigmoidf_(gv);
                    g_y[(size_t)(bL + t0 + t) * DIn + d] = roundtf(yv);
                }
            }
        }
        if (c + 1 < NC) do_store(buf ^ 1);
        __syncthreads();
    }
}

// ============================================================================
extern "C" void kernel_launch(void* const* d_in, const int* in_sizes, int n_in,
                              void* d_out, int out_size)
{
    const float* x          = (const float*)d_in[0];
    const float* in_proj_w  = (const float*)d_in[1];
    const float* conv_w     = (const float*)d_in[2];
    const float* conv_b     = (const float*)d_in[3];
    const float* x_proj_w   = (const float*)d_in[4];
    const float* dt_proj_w  = (const float*)d_in[5];
    const float* dt_proj_b  = (const float*)d_in[6];
    const float* out_proj_w = (const float*)d_in[7];
    const float* A_log      = (const float*)d_in[8];
    const float* D_param    = (const float*)d_in[9];
    float* out = (float*)d_out;

    float *proj, *h, *dtraw, *dt, *y, *xr, *w1t, *w2t, *w3t, *wxt, *part;
    cudaGetSymbolAddress((void**)&proj,  g_proj);
    cudaGetSymbolAddress((void**)&h,     g_h);
    cudaGetSymbolAddress((void**)&dtraw, g_dtraw);
    cudaGetSymbolAddress((void**)&dt,    g_dt);
    cudaGetSymbolAddress((void**)&y,     g_y);
    cudaGetSymbolAddress((void**)&xr,    g_xr);
    cudaGetSymbolAddress((void**)&w1t,   g_w1);
    cudaGetSymbolAddress((void**)&w2t,   g_w2);
    cudaGetSymbolAddress((void**)&w3t,   g_w3);
    cudaGetSymbolAddress((void**)&wxt,   g_wx);
    cudaGetSymbolAddress((void**)&part,  g_part);

    cudaFuncSetAttribute(tgemm<0>, cudaFuncAttributeMaxDynamicSharedMemorySize, TG_SMEM);
    cudaFuncSetAttribute(tgemm<1>, cudaFuncAttributeMaxDynamicSharedMemorySize, TG_SMEM);

    // 0) fused preprocessing (round x, transpose+round 4 weight matrices)
    fused_pre<<<NB_PRE, 256>>>(x, in_proj_w, dt_proj_w, out_proj_w, x_proj_w);

    // 1) proj = x @ in_proj_w   [4096,3072], K=768
    tgemm<0><<<dim3((2 * DIn) / 128, BLn / 128), 256, TG_SMEM>>>(
        xr, Hn, w1t, Hn, proj, 2 * DIn, Hn, nullptr, 0);

    // 2) depthwise causal conv + SiLU -> g_h
    conv_silu<<<(BLn / 4) * (DIn / 4) / 256, 256>>>(proj, conv_w, conv_b, h);

    // 3) x_proj via tensor cores, split-K=8 into partials, then reduce
    tgemm<0><<<dim3(1, BLn / 128, XKS), 256, TG_SMEM>>>(
        h, DIn, wxt, DIn, part, XNP, XKC, nullptr, (size_t)BLn * XNP);
    xreduce<<<(BLn * SP + 255) / 256, 256>>>();

    // 4) dt = softplus(dt_raw @ dt_proj_w + b)   [4096,1536], K=64 (zero-padded)
    tgemm<1><<<dim3(DIn / 128, BLn / 128), 256, TG_SMEM>>>(
        dtraw, RnP, w2t, RnP, dt, DIn, RnP, dt_proj_b, 0);

    // 5) selective scan (+ skip + gating)
    scan_kernel<<<Bn * (DIn / 8), 128>>>(A_log, D_param);

    // 6) out = y @ out_proj_w   [4096,768], K=1536
    tgemm<0><<<dim3(Hn / 128, BLn / 128), 256, TG_SMEM>>>(
        y, DIn, w3t, DIn, out, Hn, DIn, nullptr, 0);
}

// round 15
// speedup vs baseline: 1.2663x; 1.1531x over previous
#include <cuda_runtime.h>
#include <cuda_fp16.h>
#include <cstdint>
#include <cstddef>

#define Bn   2
#define Ln   2048
#define Hn   768
#define DIn  1536
#define Nn   16
#define Rn   48
#define RnP  64          /* dt K padded to 64 for BK=32 */
#define BLn  (Bn*Ln)     /* 4096 */
#define SP   (Rn + 2*Nn) /* 80 */
#define XNP  128         /* x_proj N padded 80 -> 128 */
#define XKS  8           /* x_proj K splits */
#define XKC  (DIn / XKS) /* 192 */

// -------- scratch (static device globals; zero-initialized at load) --------
__device__ float  g_proj [(size_t)BLn * 2 * DIn];  // in_proj output (h | gate)
__device__ float  g_h    [(size_t)BLn * DIn];      // conv+silu output (fp32, for scan)
__device__ __half g_hh   [(size_t)BLn * DIn];      // conv+silu output (fp16, for xproj GEMM)
__device__ float  g_ssm  [(size_t)BLn * SP];       // x_proj output (dt_raw|B|C)
__device__ float  g_part [(size_t)XKS * BLn * XNP];// x_proj split-K partials
__device__ __half g_dtraw[(size_t)BLn * RnP];      // fp16 dt_raw, K-padded (cols 48..63 stay 0)
__device__ float  g_dt   [(size_t)BLn * DIn];      // softplus(dt)
__device__ __half g_y    [(size_t)BLn * DIn];      // scan output (fp16)
__device__ __half g_xr   [(size_t)BLn * Hn];       // fp16 x
__device__ __half g_w1   [(size_t)Hn * 2 * DIn];   // in_proj_w^T  [3072][768], fp16
__device__ __half g_w2   [(size_t)DIn * RnP];      // dt_proj_w^T  [1536][64],  fp16 (pad 0)
__device__ __half g_w3   [(size_t)DIn * Hn];       // out_proj_w^T [768][1536], fp16
__device__ __half g_wx   [(size_t)XNP * DIn];      // x_proj_w^T   [128][1536], fp16 (rows 80+ zero)

__device__ __forceinline__ float sigmoidf_(float x) { return 1.f / (1.f + __expf(-x)); }
__device__ __forceinline__ float softplusf_(float x) {
    return fmaxf(x, 0.f) + log1pf(__expf(-fabsf(x)));
}
__device__ __forceinline__ void cp16s(uint32_t sa, const void* g) {
    asm volatile("cp.async.cg.shared.global [%0], [%1], 16;\n" :: "r"(sa), "l"(g));
}
__device__ __forceinline__ void cp_commit() {
    asm volatile("cp.async.commit_group;\n");
}
template<int NN>
__device__ __forceinline__ void cp_wait() {
    asm volatile("cp.async.wait_group %0;\n" :: "n"(NN));
}
__device__ __forceinline__ uint32_t smem_u32(const void* p) {
    return (uint32_t)__cvta_generic_to_shared(p);
}
__device__ __forceinline__ void ldsm_x4(uint32_t& r0, uint32_t& r1, uint32_t& r2,
                                        uint32_t& r3, uint32_t a) {
    asm volatile("ldmatrix.sync.aligned.m8n8.x4.shared.b16 {%0,%1,%2,%3}, [%4];"
                 : "=r"(r0), "=r"(r1), "=r"(r2), "=r"(r3) : "r"(a));
}

// ============================================================================
// Fused preprocessing: one launch (x -> fp16 | 4 weight transposes -> fp16).
// ============================================================================
#define S0   ((size_t)BLn * Hn)
#define NBX  ((int)(S0 / 8 / 256))                          /* 1536 */
#define NBW1 ((2 * DIn / 32) * (Hn / 32))                    /* 2304 */
#define NBW2 ((DIn / 32) * ((Rn + 31) / 32))                 /* 96   */
#define NBW3 ((Hn / 32) * (DIn / 32))                        /* 1152 */
#define NBW4 (((SP + 31) / 32) * (DIn / 32))                 /* 144  */
#define NB_PRE (NBX + NBW1 + NBW2 + NBW3 + NBW4)

__device__ __forceinline__ void transpose_tile_h(
    const float* __restrict__ src, __half* __restrict__ dst,
    int R, int C, int Rstride, int bx, int by, float (*t)[33])
{
    const int tx = threadIdx.x & 31;
    const int ty = threadIdx.x >> 5;
#pragma unroll
    for (int i = 0; i < 32; i += 8) {
        int r = (by << 5) + ty + i, c = (bx << 5) + tx;
        if (r < R && c < C) t[ty + i][tx] = src[(size_t)r * C + c];
    }
    __syncthreads();
#pragma unroll
    for (int i = 0; i < 32; i += 8) {
        int r = (bx << 5) + ty + i, c = (by << 5) + tx;
        if (r < C && c < R) dst[(size_t)r * Rstride + c] = __float2half(t[tx][ty + i]);
    }
}

__global__ __launch_bounds__(256)
void fused_pre(const float* __restrict__ x,
               const float* __restrict__ in_proj_w,
               const float* __restrict__ dt_proj_w,
               const float* __restrict__ out_proj_w,
               const float* __restrict__ x_proj_w)
{
    __shared__ float t[32][33];
    int bid = blockIdx.x;

    if (bid < NBX) {
        size_t i = ((size_t)bid * 256 + threadIdx.x) * 8;
        float4 a = *(const float4*)(x + i);
        float4 b = *(const float4*)(x + i + 4);
        __half2 h0 = __floats2half2_rn(a.x, a.y);
        __half2 h1 = __floats2half2_rn(a.z, a.w);
        __half2 h2 = __floats2half2_rn(b.x, b.y);
        __half2 h3 = __floats2half2_rn(b.z, b.w);
        uint4 o;
        o.x = *(uint32_t*)&h0; o.y = *(uint32_t*)&h1;
        o.z = *(uint32_t*)&h2; o.w = *(uint32_t*)&h3;
        *(uint4*)(g_xr + i) = o;
        return;
    }
    bid -= NBX;
    if (bid < NBW1) {
        const int nbx = 2 * DIn / 32;
        transpose_tile_h(in_proj_w, g_w1, Hn, 2 * DIn, Hn, bid % nbx, bid / nbx, t);
        return;
    }
    bid -= NBW1;
    if (bid < NBW2) {
        const int nbx = DIn / 32;
        transpose_tile_h(dt_proj_w, g_w2, Rn, DIn, RnP, bid % nbx, bid / nbx, t);
        return;
    }
    bid -= NBW2;
    if (bid < NBW3) {
        const int nbx = Hn / 32;
        transpose_tile_h(out_proj_w, g_w3, DIn, Hn, DIn, bid % nbx, bid / nbx, t);
        return;
    }
    bid -= NBW3;
    {
        const int nbx = (SP + 31) / 32;   // 3
        transpose_tile_h(x_proj_w, g_wx, DIn, SP, DIn, bid % nbx, bid / nbx, t);
    }
}

// ============================================================================
// xreduce: sum 8 split-K partials -> g_ssm; fp16 dt_raw cols -> g_dtraw.
// ============================================================================
__global__ __launch_bounds__(256)
void xreduce()
{
    int i = blockIdx.x * blockDim.x + threadIdx.x;   // over BLn*SP
    if (i >= BLn * SP) return;
    int row = i / SP, col = i - row * SP;
    float s = 0.f;
#pragma unroll
    for (int z = 0; z < XKS; z++)
        s += g_part[(size_t)z * BLn * XNP + (size_t)row * XNP + col];
    g_ssm[i] = s;
    if (col < Rn) g_dtraw[(size_t)row * RnP + col] = __float2half(s);
}

// ============================================================================
// FP16 mma.sync GEMM (m16n8k16): 128x128 CTA, 8 warps of 64x32, BK=32,
// 4-stage cp.async, ldmatrix x4.  C[M,N] = A[M,K](lda) @ Bt[N,K](ldb)^T.
// A,Bt fp16; accum fp32. blockIdx.z = K-split (A,Bt +z*K; C +z*csplit).
// EPI==1: C = softplus(C + bias[n]).
// smem/stage: 2 tiles x 128 rows x 40 halfs = 20480 B; 4 stages = 81920 B.
// ============================================================================
#define TG_STAGES 4
#define TG_TSZ (128 * 40)                    /* halfs per operand tile */
#define TG_STG (2 * TG_TSZ)                  /* halfs per stage */
#define TG_SMEM (TG_STAGES * TG_STG * 2)     /* 81920 bytes */

template<int EPI>
__global__ __launch_bounds__(256, 2)
void tgemm(const __half* __restrict__ A, int lda,
           const __half* __restrict__ Bt, int ldb,
           float* __restrict__ C, int N, int K,
           const float* __restrict__ bias, size_t csplit)
{
    extern __shared__ __half smem[];

    const int tid  = threadIdx.x;
    const int lane = tid & 31;
    const int warp = tid >> 5;
    const int wm   = warp >> 2;
    const int wn   = warp & 3;
    const int m0   = wm * 64;
    const int n0   = wn * 32;
    const int g    = lane >> 2;
    const int c    = lane & 3;

    const int bm = blockIdx.y << 7;
    const int bn = blockIdx.x << 7;
    const int kz = blockIdx.z;
    A  += (size_t)kz * K;
    Bt += (size_t)kz * K;
    C  += (size_t)kz * csplit;

    const uint32_t smem0 = smem_u32(smem);

    // cp.async: per tile 512 chunks of 16B (128 rows x 4 chunks); 2/thread.
    uint32_t sOff[2];
    const __half* Ap[2];
    const __half* Bp[2];
#pragma unroll
    for (int i = 0; i < 2; i++) {
        const int ch  = tid * 2 + i;
        const int row = ch >> 2;
        const int kh  = (ch & 3) << 3;      // half offset, 8 halfs = 16B
        sOff[i] = (uint32_t)(row * 40 + kh) * 2;
        Ap[i] = A  + (size_t)(bm + row) * lda + kh;
        Bp[i] = Bt + (size_t)(bn + row) * ldb + kh;
    }

    // ldmatrix bases (pad 40 halfs = 80 B rows; conflict-free phases)
    const int arow = m0 + (lane & 7) + ((lane & 8) ? 8 : 0);
    const int acol = (lane & 16) ? 8 : 0;   // k-half offset in halfs
    const uint32_t aBase = (uint32_t)(arow * 40 + acol) * 2;
    const int brow = n0 + (lane & 7) + ((lane & 16) ? 8 : 0);
    const int bcol = (lane & 8) ? 8 : 0;
    const uint32_t bBase = (uint32_t)(brow * 40 + bcol) * 2;

    float acc[4][4][4];
#pragma unroll
    for (int i = 0; i < 4; i++)
#pragma unroll
        for (int j = 0; j < 4; j++)
#pragma unroll
            for (int q = 0; q < 4; q++) acc[i][j][q] = 0.f;

    const int nk = K >> 5;   // BK = 32 halfs

    auto load_stage = [&](int kt, int s) {
        const uint32_t stA = smem0 + (uint32_t)(s * TG_STG) * 2;
        const uint32_t stB = stA + TG_TSZ * 2;
        const int k0 = kt << 5;
#pragma unroll
        for (int i = 0; i < 2; i++) {
            cp16s(stA + sOff[i], Ap[i] + k0);
            cp16s(stB + sOff[i], Bp[i] + k0);
        }
    };
    auto compute = [&](int s) {
        const uint32_t stA = smem0 + (uint32_t)(s * TG_STG) * 2;
        const uint32_t stB = stA + TG_TSZ * 2;
#pragma unroll
        for (int ks = 0; ks < 2; ks++) {        // two k16 steps per BK=32
            const uint32_t kb = (uint32_t)(ks << 4) * 2;   // 16 halfs = 32 B
            uint32_t af[4][4], bf[4][2];
#pragma unroll
            for (int i = 0; i < 4; i++)
                ldsm_x4(af[i][0], af[i][1], af[i][2], af[i][3],
                        stA + aBase + (uint32_t)(i * 16 * 40) * 2 + kb);
#pragma unroll
            for (int jj = 0; jj < 2; jj++)
                ldsm_x4(bf[2 * jj][0], bf[2 * jj][1], bf[2 * jj + 1][0], bf[2 * jj + 1][1],
                        stB + bBase + (uint32_t)(jj * 16 * 40) * 2 + kb);
#pragma unroll
            for (int i = 0; i < 4; i++)
#pragma unroll
                for (int j = 0; j < 4; j++)
                    asm volatile(
                        "mma.sync.aligned.m16n8k16.row.col.f32.f16.f16.f32 "
                        "{%0,%1,%2,%3}, {%4,%5,%6,%7}, {%8,%9}, {%0,%1,%2,%3};\n"
                        : "+f"(acc[i][j][0]), "+f"(acc[i][j][1]),
                          "+f"(acc[i][j][2]), "+f"(acc[i][j][3])
                        : "r"(af[i][0]), "r"(af[i][1]), "r"(af[i][2]), "r"(af[i][3]),
                          "r"(bf[j][0]), "r"(bf[j][1]));
        }
    };

#pragma unroll
    for (int s = 0; s < TG_STAGES - 1; s++) {
        if (s < nk) load_stage(s, s);
        cp_commit();
    }
    for (int kt = 0; kt < nk; ++kt) {
        cp_wait<TG_STAGES - 2>();
        __syncthreads();
        const int nxt = kt + TG_STAGES - 1;
        if (nxt < nk) load_stage(nxt, nxt & (TG_STAGES - 1));
        cp_commit();
        compute(kt & (TG_STAGES - 1));
    }

#pragma unroll
    for (int i = 0; i < 4; i++) {
        const int r0 = bm + m0 + i * 16 + g;
#pragma unroll
        for (int j = 0; j < 4; j++) {
            const int col = bn + n0 + j * 8 + 2 * c;
            float v00 = acc[i][j][0], v01 = acc[i][j][1];
            float v10 = acc[i][j][2], v11 = acc[i][j][3];
            if (EPI == 1) {
                const float b0v = bias[col], b1v = bias[col + 1];
                v00 = softplusf_(v00 + b0v);
                v01 = softplusf_(v01 + b1v);
                v10 = softplusf_(v10 + b0v);
                v11 = softplusf_(v11 + b1v);
            }
            *(float2*)&C[(size_t)r0 * N + col]       = make_float2(v00, v01);
            *(float2*)&C[(size_t)(r0 + 8) * N + col] = make_float2(v10, v11);
        }
    }
}

// ============================================================================
// Depthwise causal conv (K=4) + bias + SiLU. 4 channels x 4 timesteps/thread.
// Writes fp32 g_h (scan) + fp16 g_hh (xproj GEMM).
// ============================================================================
__global__ __launch_bounds__(256)
void conv_silu(const float* __restrict__ proj,
               const float* __restrict__ cw,
               const float* __restrict__ cb)
{
    int idx = blockIdx.x * blockDim.x + threadIdx.x;   // over (BLn/4)*(DIn/4)
    int d4  = (idx % (DIn / 4)) << 2;
    int bt4 = idx / (DIn / 4);
    int tb  = (bt4 & (Ln / 4 - 1)) << 2;
    size_t row0 = (size_t)bt4 * 4;

    const int s = 2 * DIn;
    const float* p = proj + row0 * s + d4;
    float4 z = make_float4(0.f, 0.f, 0.f, 0.f);
    float4 r[7];
#pragma unroll
    for (int j = 0; j < 7; j++) {
        int tt = tb - 3 + j;
        r[j] = (tt >= 0) ? *(const float4*)(p + (ptrdiff_t)(j - 3) * s) : z;
    }
    float4 cbv = *(const float4*)(cb + d4);
    float4 w0 = *(const float4*)(cw + (d4 + 0) * 4);
    float4 w1 = *(const float4*)(cw + (d4 + 1) * 4);
    float4 w2 = *(const float4*)(cw + (d4 + 2) * 4);
    float4 w3 = *(const float4*)(cw + (d4 + 3) * 4);

#pragma unroll
    for (int i = 0; i < 4; i++) {
        float4 o;
        o.x = fmaf(r[i].x, w0.x, fmaf(r[i+1].x, w0.y, fmaf(r[i+2].x, w0.z, fmaf(r[i+3].x, w0.w, cbv.x))));
        o.y = fmaf(r[i].y, w1.x, fmaf(r[i+1].y, w1.y, fmaf(r[i+2].y, w1.z, fmaf(r[i+3].y, w1.w, cbv.y))));
        o.z = fmaf(r[i].z, w2.x, fmaf(r[i+1].z, w2.y, fmaf(r[i+2].z, w2.z, fmaf(r[i+3].z, w2.w, cbv.z))));
        o.w = fmaf(r[i].w, w3.x, fmaf(r[i+1].w, w3.y, fmaf(r[i+2].w, w3.z, fmaf(r[i+3].w, w3.w, cbv.w))));
        o.x = o.x * sigmoidf_(o.x);
        o.y = o.y * sigmoidf_(o.y);
        o.z = o.z * sigmoidf_(o.z);
        o.w = o.w * sigmoidf_(o.w);
        *(float4*)(g_h + (row0 + i) * DIn + d4) = o;
        __half2 h0 = __floats2half2_rn(o.x, o.y);
        __half2 h1 = __floats2half2_rn(o.z, o.w);
        uint2 u; u.x = *(uint32_t*)&h0; u.y = *(uint32_t*)&h1;
        *(uint2*)(g_hh + (row0 + i) * DIn + d4) = u;
    }
}

// ============================================================================
// Fused selective scan + skip + gating. 64-step chunks, 8-t batched shuffles.
// Writes fp16 y.
// ============================================================================
#define SC_T 64
__global__ __launch_bounds__(128)
void scan_kernel(const float* __restrict__ Alog, const float* __restrict__ Dp)
{
    __shared__ float s_h [2][SC_T][8];
    __shared__ float s_dt[2][SC_T][8];
    __shared__ float s_g [2][SC_T][8];
    __shared__ float s_B [2][SC_T][16];
    __shared__ float s_C [2][SC_T][16];

    const int tid  = threadIdx.x;
    const int lane = tid & 31;
    const int w    = tid >> 5;
    const int n    = lane & 15;
    const int half = lane >> 4;
    const int dl   = (w << 1) + half;
    const int blk  = blockIdx.x;
    const int b    = blk / (DIn / 8);
    const int d0   = (blk % (DIn / 8)) << 3;
    const int d    = d0 + dl;
    const int bL   = b * Ln;

    const float A_dn = -__expf(Alog[d * Nn + n]);
    const float Dv   = Dp[d];
    float state = 0.f;

    float rh[4], rdt[4], rg[4], rB[8], rC[8];

    auto do_load = [&](int c) {
        int t0 = c * SC_T;
#pragma unroll
        for (int j = 0; j < 4; j++) {
            int e = tid + (j << 7);
            int t = e >> 3, dd = e & 7;
            int row = bL + t0 + t;
            rh[j]  = g_h [(size_t)row * DIn + d0 + dd];
            rdt[j] = g_dt[(size_t)row * DIn + d0 + dd];
            rg[j]  = g_proj[(size_t)row * (2 * DIn) + DIn + d0 + dd];
        }
#pragma unroll
        for (int j = 0; j < 8; j++) {
            int e = tid + (j << 7);
            int t = e >> 4, nn = e & 15;
            int row = bL + t0 + t;
            rB[j] = g_ssm[(size_t)row * SP + Rn + nn];
            rC[j] = g_ssm[(size_t)row * SP + Rn + Nn + nn];
        }
    };
    auto do_store = [&](int buf) {
#pragma unroll
        for (int j = 0; j < 4; j++) {
            int e = tid + (j << 7);
            int t = e >> 3, dd = e & 7;
            s_h [buf][t][dd] = rh[j];
            s_dt[buf][t][dd] = rdt[j];
            s_g [buf][t][dd] = rg[j];
        }
#pragma unroll
        for (int j = 0; j < 8; j++) {
            int e = tid + (j << 7);
            int t = e >> 4, nn = e & 15;
            s_B[buf][t][nn] = rB[j];
            s_C[buf][t][nn] = rC[j];
        }
    };

    do_load(0);
    do_store(0);
    __syncthreads();

    const int NC = Ln / SC_T;
    for (int c = 0; c < NC; c++) {
        const int buf = c & 1;
        if (c + 1 < NC) do_load(c + 1);
        const int t0 = c * SC_T;
#pragma unroll
        for (int tb = 0; tb < SC_T; tb += 8) {
            float p[8], hs[8];
#pragma unroll
            for (int tt = 0; tt < 8; tt++) {
                const int t = tb + tt;
                float dtv = s_dt[buf][t][dl];
                float hv  = s_h [buf][t][dl];
                float Bv  = s_B [buf][t][n];
                float Cv  = s_C [buf][t][n];
                float dA  = __expf(A_dn * dtv);
                state = fmaf(dA, state, Bv * hv);
                p[tt]  = state * Cv;
                hs[tt] = hv;
            }
#pragma unroll
            for (int st = 8; st >= 1; st >>= 1)
#pragma unroll
                for (int tt = 0; tt < 8; tt++)
                    p[tt] += __shfl_xor_sync(0xffffffffu, p[tt], st);
            if (n == 0) {
#pragma unroll
                for (int tt = 0; tt < 8; tt++) {
                    const int t = tb + tt;
                    float gv = s_g[buf][t][dl];
                    float yv = (p[tt] + hs[tt] * Dv) * gv * sigmoidf_(gv);
                    g_y[(size_t)(bL + t0 + t) * DIn + d] = __float2half(yv);
                }
            }
        }
        if (c + 1 < NC) do_store(buf ^ 1);
        __syncthreads();
    }
}

// ============================================================================
extern "C" void kernel_launch(void* const* d_in, const int* in_sizes, int n_in,
                              void* d_out, int out_size)
{
    const float* x          = (const float*)d_in[0];
    const float* in_proj_w  = (const float*)d_in[1];
    const float* conv_w     = (const float*)d_in[2];
    const float* conv_b     = (const float*)d_in[3];
    const float* x_proj_w   = (const float*)d_in[4];
    const float* dt_proj_w  = (const float*)d_in[5];
    const float* dt_proj_b  = (const float*)d_in[6];
    const float* out_proj_w = (const float*)d_in[7];
    const float* A_log      = (const float*)d_in[8];
    const float* D_param    = (const float*)d_in[9];
    float* out = (float*)d_out;

    float *proj, *dt, *part;
    __half *hh, *dtraw, *y, *xr, *w1t, *w2t, *w3t, *wxt;
    cudaGetSymbolAddress((void**)&proj,  g_proj);
    cudaGetSymbolAddress((void**)&hh,    g_hh);
    cudaGetSymbolAddress((void**)&dtraw, g_dtraw);
    cudaGetSymbolAddress((void**)&dt,    g_dt);
    cudaGetSymbolAddress((void**)&y,     g_y);
    cudaGetSymbolAddress((void**)&xr,    g_xr);
    cudaGetSymbolAddress((void**)&w1t,   g_w1);
    cudaGetSymbolAddress((void**)&w2t,   g_w2);
    cudaGetSymbolAddress((void**)&w3t,   g_w3);
    cudaGetSymbolAddress((void**)&wxt,   g_wx);
    cudaGetSymbolAddress((void**)&part,  g_part);

    cudaFuncSetAttribute(tgemm<0>, cudaFuncAttributeMaxDynamicSharedMemorySize, TG_SMEM);
    cudaFuncSetAttribute(tgemm<1>, cudaFuncAttributeMaxDynamicSharedMemorySize, TG_SMEM);

    // 0) fused preprocessing (x -> fp16, 4 weight transposes -> fp16)
    fused_pre<<<NB_PRE, 256>>>(x, in_proj_w, dt_proj_w, out_proj_w, x_proj_w);

    // 1) proj = x @ in_proj_w   [4096,3072], K=768  (fp16 MMA)
    tgemm<0><<<dim3((2 * DIn) / 128, BLn / 128), 256, TG_SMEM>>>(
        xr, Hn, w1t, Hn, proj, 2 * DIn, Hn, nullptr, 0);

    // 2) depthwise causal conv + SiLU -> g_h (fp32) + g_hh (fp16)
    conv_silu<<<(BLn / 4) * (DIn / 4) / 256, 256>>>(proj, conv_w, conv_b);

    // 3) x_proj via fp16 MMA, split-K=8 into partials, then reduce
    tgemm<0><<<dim3(1, BLn / 128, XKS), 256, TG_SMEM>>>(
        hh, DIn, wxt, DIn, part, XNP, XKC, nullptr, (size_t)BLn * XNP);
    xreduce<<<(BLn * SP + 255) / 256, 256>>>();

    // 4) dt = softplus(dt_raw @ dt_proj_w + b)   [4096,1536], K=64 (zero-padded)
    tgemm<1><<<dim3(DIn / 128, BLn / 128), 256, TG_SMEM>>>(
        dtraw, RnP, w2t, RnP, dt, DIn, RnP, dt_proj_b, 0);

    // 5) selective scan (+ skip + gating) -> fp16 y
    scan_kernel<<<Bn * (DIn / 8), 128>>>(A_log, D_param);

    // 6) out = y @ out_proj_w   [4096,768], K=1536  (fp16 MMA)
    tgemm<0><<<dim3(Hn / 128, BLn / 128), 256, TG_SMEM>>>(
        y, DIn, w3t, DIn, out, Hn, DIn, nullptr, 0);
}

// round 16
// speedup vs baseline: 1.3024x; 1.0285x over previous
#include <cuda_runtime.h>
#include <cuda_fp16.h>
#include <cstdint>
#include <cstddef>

#define Bn   2
#define Ln   2048
#define Hn   768
#define DIn  1536
#define Nn   16
#define Rn   48
#define RnP  64          /* dt K padded to 64 for BK=32 */
#define BLn  (Bn*Ln)     /* 4096 */
#define SP   (Rn + 2*Nn) /* 80 */
#define XNP  128         /* x_proj N padded 80 -> 128 */
#define XKS  8           /* x_proj K splits */
#define XKC  (DIn / XKS) /* 192 */

// -------- scratch (static device globals; zero-initialized at load) --------
__device__ __half g_proj [(size_t)BLn * 2 * DIn];  // in_proj output (h | gate), fp16
__device__ __half g_hh   [(size_t)BLn * DIn];      // conv+silu output, fp16
__device__ float  g_ssm  [(size_t)BLn * SP];       // x_proj output (dt_raw|B|C)
__device__ float  g_part [(size_t)XKS * BLn * XNP];// x_proj split-K partials
__device__ __half g_dtraw[(size_t)BLn * RnP];      // fp16 dt_raw, K-padded (cols 48..63 stay 0)
__device__ __half g_dt   [(size_t)BLn * DIn];      // softplus(dt), fp16
__device__ __half g_y    [(size_t)BLn * DIn];      // scan output (fp16)
__device__ __half g_xr   [(size_t)BLn * Hn];       // fp16 x
__device__ __half g_w1   [(size_t)Hn * 2 * DIn];   // in_proj_w^T  [3072][768], fp16
__device__ __half g_w2   [(size_t)DIn * RnP];      // dt_proj_w^T  [1536][64],  fp16 (pad 0)
__device__ __half g_w3   [(size_t)DIn * Hn];       // out_proj_w^T [768][1536], fp16
__device__ __half g_wx   [(size_t)XNP * DIn];      // x_proj_w^T   [128][1536], fp16 (rows 80+ zero)

__device__ __forceinline__ float sigmoidf_(float x) { return 1.f / (1.f + __expf(-x)); }
__device__ __forceinline__ float softplusf_(float x) {
    return fmaxf(x, 0.f) + log1pf(__expf(-fabsf(x)));
}
__device__ __forceinline__ void cp16s(uint32_t sa, const void* g) {
    asm volatile("cp.async.cg.shared.global [%0], [%1], 16;\n" :: "r"(sa), "l"(g));
}
__device__ __forceinline__ void cp_commit() {
    asm volatile("cp.async.commit_group;\n");
}
template<int NN>
__device__ __forceinline__ void cp_wait() {
    asm volatile("cp.async.wait_group %0;\n" :: "n"(NN));
}
__device__ __forceinline__ uint32_t smem_u32(const void* p) {
    return (uint32_t)__cvta_generic_to_shared(p);
}
__device__ __forceinline__ void ldsm_x4(uint32_t& r0, uint32_t& r1, uint32_t& r2,
                                        uint32_t& r3, uint32_t a) {
    asm volatile("ldmatrix.sync.aligned.m8n8.x4.shared.b16 {%0,%1,%2,%3}, [%4];"
                 : "=r"(r0), "=r"(r1), "=r"(r2), "=r"(r3) : "r"(a));
}
__device__ __forceinline__ uint32_t pack_h2(float a, float b) {
    __half2 h = __floats2half2_rn(a, b);
    return *(uint32_t*)&h;
}

// ============================================================================
// Fused preprocessing: one launch (x -> fp16 | 4 weight transposes -> fp16).
// ============================================================================
#define S0   ((size_t)BLn * Hn)
#define NBX  ((int)(S0 / 8 / 256))                          /* 1536 */
#define NBW1 ((2 * DIn / 32) * (Hn / 32))                    /* 2304 */
#define NBW2 ((DIn / 32) * ((Rn + 31) / 32))                 /* 96   */
#define NBW3 ((Hn / 32) * (DIn / 32))                        /* 1152 */
#define NBW4 (((SP + 31) / 32) * (DIn / 32))                 /* 144  */
#define NB_PRE (NBX + NBW1 + NBW2 + NBW3 + NBW4)

__device__ __forceinline__ void transpose_tile_h(
    const float* __restrict__ src, __half* __restrict__ dst,
    int R, int C, int Rstride, int bx, int by, float (*t)[33])
{
    const int tx = threadIdx.x & 31;
    const int ty = threadIdx.x >> 5;
#pragma unroll
    for (int i = 0; i < 32; i += 8) {
        int r = (by << 5) + ty + i, c = (bx << 5) + tx;
        if (r < R && c < C) t[ty + i][tx] = src[(size_t)r * C + c];
    }
    __syncthreads();
#pragma unroll
    for (int i = 0; i < 32; i += 8) {
        int r = (bx << 5) + ty + i, c = (by << 5) + tx;
        if (r < C && c < R) dst[(size_t)r * Rstride + c] = __float2half(t[tx][ty + i]);
    }
}

__global__ __launch_bounds__(256)
void fused_pre(const float* __restrict__ x,
               const float* __restrict__ in_proj_w,
               const float* __restrict__ dt_proj_w,
               const float* __restrict__ out_proj_w,
               const float* __restrict__ x_proj_w)
{
    __shared__ float t[32][33];
    int bid = blockIdx.x;

    if (bid < NBX) {
        size_t i = ((size_t)bid * 256 + threadIdx.x) * 8;
        float4 a = *(const float4*)(x + i);
        float4 b = *(const float4*)(x + i + 4);
        uint4 o;
        o.x = pack_h2(a.x, a.y); o.y = pack_h2(a.z, a.w);
        o.z = pack_h2(b.x, b.y); o.w = pack_h2(b.z, b.w);
        *(uint4*)(g_xr + i) = o;
        return;
    }
    bid -= NBX;
    if (bid < NBW1) {
        const int nbx = 2 * DIn / 32;
        transpose_tile_h(in_proj_w, g_w1, Hn, 2 * DIn, Hn, bid % nbx, bid / nbx, t);
        return;
    }
    bid -= NBW1;
    if (bid < NBW2) {
        const int nbx = DIn / 32;
        transpose_tile_h(dt_proj_w, g_w2, Rn, DIn, RnP, bid % nbx, bid / nbx, t);
        return;
    }
    bid -= NBW2;
    if (bid < NBW3) {
        const int nbx = Hn / 32;
        transpose_tile_h(out_proj_w, g_w3, DIn, Hn, DIn, bid % nbx, bid / nbx, t);
        return;
    }
    bid -= NBW3;
    {
        const int nbx = (SP + 31) / 32;   // 3
        transpose_tile_h(x_proj_w, g_wx, DIn, SP, DIn, bid % nbx, bid / nbx, t);
    }
}

// ============================================================================
// xreduce: sum 8 split-K partials -> g_ssm; fp16 dt_raw cols -> g_dtraw.
// ============================================================================
__global__ __launch_bounds__(256)
void xreduce()
{
    int i = blockIdx.x * blockDim.x + threadIdx.x;   // over BLn*SP
    if (i >= BLn * SP) return;
    int row = i / SP, col = i - row * SP;
    float s = 0.f;
#pragma unroll
    for (int z = 0; z < XKS; z++)
        s += g_part[(size_t)z * BLn * XNP + (size_t)row * XNP + col];
    g_ssm[i] = s;
    if (col < Rn) g_dtraw[(size_t)row * RnP + col] = __float2half(s);
}

// ============================================================================
// FP16 mma.sync GEMM (m16n8k16): 128x128 CTA, 8 warps of 64x32, BK=32,
// 4-stage cp.async, ldmatrix x4.  C[M,N] = A[M,K](lda) @ Bt[N,K](ldb)^T.
// A,Bt fp16; accum fp32. blockIdx.z = K-split (A,Bt +z*K; C +z*csplit).
// EPI==1: C = softplus(C + bias[n]).  HOUT==1: fp16 output, else fp32.
// ============================================================================
#define TG_STAGES 4
#define TG_TSZ (128 * 40)
#define TG_STG (2 * TG_TSZ)
#define TG_SMEM (TG_STAGES * TG_STG * 2)     /* 81920 bytes */

template<int EPI, int HOUT>
__global__ __launch_bounds__(256, 2)
void tgemm(const __half* __restrict__ A, int lda,
           const __half* __restrict__ Bt, int ldb,
           void* __restrict__ Cv, int N, int K,
           const float* __restrict__ bias, size_t csplit)
{
    extern __shared__ __half smem[];

    const int tid  = threadIdx.x;
    const int lane = tid & 31;
    const int warp = tid >> 5;
    const int wm   = warp >> 2;
    const int wn   = warp & 3;
    const int m0   = wm * 64;
    const int n0   = wn * 32;
    const int g    = lane >> 2;
    const int c    = lane & 3;

    const int bm = blockIdx.y << 7;
    const int bn = blockIdx.x << 7;
    const int kz = blockIdx.z;
    A  += (size_t)kz * K;
    Bt += (size_t)kz * K;

    const uint32_t smem0 = smem_u32(smem);

    uint32_t sOff[2];
    const __half* Ap[2];
    const __half* Bp[2];
#pragma unroll
    for (int i = 0; i < 2; i++) {
        const int ch  = tid * 2 + i;
        const int row = ch >> 2;
        const int kh  = (ch & 3) << 3;
        sOff[i] = (uint32_t)(row * 40 + kh) * 2;
        Ap[i] = A  + (size_t)(bm + row) * lda + kh;
        Bp[i] = Bt + (size_t)(bn + row) * ldb + kh;
    }

    const int arow = m0 + (lane & 7) + ((lane & 8) ? 8 : 0);
    const int acol = (lane & 16) ? 8 : 0;
    const uint32_t aBase = (uint32_t)(arow * 40 + acol) * 2;
    const int brow = n0 + (lane & 7) + ((lane & 16) ? 8 : 0);
    const int bcol = (lane & 8) ? 8 : 0;
    const uint32_t bBase = (uint32_t)(brow * 40 + bcol) * 2;

    float acc[4][4][4];
#pragma unroll
    for (int i = 0; i < 4; i++)
#pragma unroll
        for (int j = 0; j < 4; j++)
#pragma unroll
            for (int q = 0; q < 4; q++) acc[i][j][q] = 0.f;

    const int nk = K >> 5;

    auto load_stage = [&](int kt, int s) {
        const uint32_t stA = smem0 + (uint32_t)(s * TG_STG) * 2;
        const uint32_t stB = stA + TG_TSZ * 2;
        const int k0 = kt << 5;
#pragma unroll
        for (int i = 0; i < 2; i++) {
            cp16s(stA + sOff[i], Ap[i] + k0);
            cp16s(stB + sOff[i], Bp[i] + k0);
        }
    };
    auto compute = [&](int s) {
        const uint32_t stA = smem0 + (uint32_t)(s * TG_STG) * 2;
        const uint32_t stB = stA + TG_TSZ * 2;
#pragma unroll
        for (int ks = 0; ks < 2; ks++) {
            const uint32_t kb = (uint32_t)(ks << 4) * 2;
            uint32_t af[4][4], bf[4][2];
#pragma unroll
            for (int i = 0; i < 4; i++)
                ldsm_x4(af[i][0], af[i][1], af[i][2], af[i][3],
                        stA + aBase + (uint32_t)(i * 16 * 40) * 2 + kb);
#pragma unroll
            for (int jj = 0; jj < 2; jj++)
                ldsm_x4(bf[2 * jj][0], bf[2 * jj][1], bf[2 * jj + 1][0], bf[2 * jj + 1][1],
                        stB + bBase + (uint32_t)(jj * 16 * 40) * 2 + kb);
#pragma unroll
            for (int i = 0; i < 4; i++)
#pragma unroll
                for (int j = 0; j < 4; j++)
                    asm volatile(
                        "mma.sync.aligned.m16n8k16.row.col.f32.f16.f16.f32 "
                        "{%0,%1,%2,%3}, {%4,%5,%6,%7}, {%8,%9}, {%0,%1,%2,%3};\n"
                        : "+f"(acc[i][j][0]), "+f"(acc[i][j][1]),
                          "+f"(acc[i][j][2]), "+f"(acc[i][j][3])
                        : "r"(af[i][0]), "r"(af[i][1]), "r"(af[i][2]), "r"(af[i][3]),
                          "r"(bf[j][0]), "r"(bf[j][1]));
        }
    };

#pragma unroll
    for (int s = 0; s < TG_STAGES - 1; s++) {
        if (s < nk) load_stage(s, s);
        cp_commit();
    }
    for (int kt = 0; kt < nk; ++kt) {
        cp_wait<TG_STAGES - 2>();
        __syncthreads();
        const int nxt = kt + TG_STAGES - 1;
        if (nxt < nk) load_stage(nxt, nxt & (TG_STAGES - 1));
        cp_commit();
        compute(kt & (TG_STAGES - 1));
    }

    // epilogue
    float*  Cf = (float*)Cv  + (size_t)kz * csplit;
    __half* Ch = (__half*)Cv + (size_t)kz * csplit;
#pragma unroll
    for (int i = 0; i < 4; i++) {
        const int r0 = bm + m0 + i * 16 + g;
#pragma unroll
        for (int j = 0; j < 4; j++) {
            const int col = bn + n0 + j * 8 + 2 * c;
            float v00 = acc[i][j][0], v01 = acc[i][j][1];
            float v10 = acc[i][j][2], v11 = acc[i][j][3];
            if (EPI == 1) {
                const float b0v = bias[col], b1v = bias[col + 1];
                v00 = softplusf_(v00 + b0v);
                v01 = softplusf_(v01 + b1v);
                v10 = softplusf_(v10 + b0v);
                v11 = softplusf_(v11 + b1v);
            }
            if (HOUT) {
                *(uint32_t*)&Ch[(size_t)r0 * N + col]       = pack_h2(v00, v01);
                *(uint32_t*)&Ch[(size_t)(r0 + 8) * N + col] = pack_h2(v10, v11);
            } else {
                *(float2*)&Cf[(size_t)r0 * N + col]       = make_float2(v00, v01);
                *(float2*)&Cf[(size_t)(r0 + 8) * N + col] = make_float2(v10, v11);
            }
        }
    }
}

// ============================================================================
// Depthwise causal conv (K=4) + bias + SiLU. 4 channels x 4 timesteps/thread.
// Reads fp16 proj (h half), writes fp16 g_hh.
// ============================================================================
__global__ __launch_bounds__(256)
void conv_silu(const float* __restrict__ cw, const float* __restrict__ cb)
{
    int idx = blockIdx.x * blockDim.x + threadIdx.x;   // over (BLn/4)*(DIn/4)
    int d4  = (idx % (DIn / 4)) << 2;
    int bt4 = idx / (DIn / 4);
    int tb  = (bt4 & (Ln / 4 - 1)) << 2;
    size_t row0 = (size_t)bt4 * 4;

    const int s = 2 * DIn;
    const __half* p = g_proj + row0 * s + d4;
    float4 z = make_float4(0.f, 0.f, 0.f, 0.f);
    float4 r[7];
#pragma unroll
    for (int j = 0; j < 7; j++) {
        int tt = tb - 3 + j;
        if (tt >= 0) {
            uint2 u = *(const uint2*)(p + (ptrdiff_t)(j - 3) * s);
            __half2 h0 = *(__half2*)&u.x, h1 = *(__half2*)&u.y;
            float2 f0 = __half22float2(h0), f1 = __half22float2(h1);
            r[j] = make_float4(f0.x, f0.y, f1.x, f1.y);
        } else r[j] = z;
    }
    float4 cbv = *(const float4*)(cb + d4);
    float4 w0 = *(const float4*)(cw + (d4 + 0) * 4);
    float4 w1 = *(const float4*)(cw + (d4 + 1) * 4);
    float4 w2 = *(const float4*)(cw + (d4 + 2) * 4);
    float4 w3 = *(const float4*)(cw + (d4 + 3) * 4);

#pragma unroll
    for (int i = 0; i < 4; i++) {
        float4 o;
        o.x = fmaf(r[i].x, w0.x, fmaf(r[i+1].x, w0.y, fmaf(r[i+2].x, w0.z, fmaf(r[i+3].x, w0.w, cbv.x))));
        o.y = fmaf(r[i].y, w1.x, fmaf(r[i+1].y, w1.y, fmaf(r[i+2].y, w1.z, fmaf(r[i+3].y, w1.w, cbv.y))));
        o.z = fmaf(r[i].z, w2.x, fmaf(r[i+1].z, w2.y, fmaf(r[i+2].z, w2.z, fmaf(r[i+3].z, w2.w, cbv.z))));
        o.w = fmaf(r[i].w, w3.x, fmaf(r[i+1].w, w3.y, fmaf(r[i+2].w, w3.z, fmaf(r[i+3].w, w3.w, cbv.w))));
        o.x = o.x * sigmoidf_(o.x);
        o.y = o.y * sigmoidf_(o.y);
        o.z = o.z * sigmoidf_(o.z);
        o.w = o.w * sigmoidf_(o.w);
        uint2 u; u.x = pack_h2(o.x, o.y); u.y = pack_h2(o.z, o.w);
        *(uint2*)(g_hh + (row0 + i) * DIn + d4) = u;
    }
}

// ============================================================================
// Fused selective scan + skip + gating. 64-step chunks, 8-t batched shuffles.
// Reads fp16 h/dt/gate (converted to fp32 at load); writes fp16 y.
// ============================================================================
#define SC_T 64
__global__ __launch_bounds__(128)
void scan_kernel(const float* __restrict__ Alog, const float* __restrict__ Dp)
{
    __shared__ float s_h [2][SC_T][8];
    __shared__ float s_dt[2][SC_T][8];
    __shared__ float s_g [2][SC_T][8];
    __shared__ float s_B [2][SC_T][16];
    __shared__ float s_C [2][SC_T][16];

    const int tid  = threadIdx.x;
    const int lane = tid & 31;
    const int w    = tid >> 5;
    const int n    = lane & 15;
    const int half = lane >> 4;
    const int dl   = (w << 1) + half;
    const int blk  = blockIdx.x;
    const int b    = blk / (DIn / 8);
    const int d0   = (blk % (DIn / 8)) << 3;
    const int d    = d0 + dl;
    const int bL   = b * Ln;

    const float A_dn = -__expf(Alog[d * Nn + n]);
    const float Dv   = Dp[d];
    float state = 0.f;

    float rh[4], rdt[4], rg[4], rB[8], rC[8];

    auto do_load = [&](int c) {
        int t0 = c * SC_T;
#pragma unroll
        for (int j = 0; j < 4; j++) {
            int e = tid + (j << 7);
            int t = e >> 3, dd = e & 7;
            int row = bL + t0 + t;
            rh[j]  = __half2float(g_hh [(size_t)row * DIn + d0 + dd]);
            rdt[j] = __half2float(g_dt [(size_t)row * DIn + d0 + dd]);
            rg[j]  = __half2float(g_proj[(size_t)row * (2 * DIn) + DIn + d0 + dd]);
        }
#pragma unroll
        for (int j = 0; j < 8; j++) {
            int e = tid + (j << 7);
            int t = e >> 4, nn = e & 15;
            int row = bL + t0 + t;
            rB[j] = g_ssm[(size_t)row * SP + Rn + nn];
            rC[j] = g_ssm[(size_t)row * SP + Rn + Nn + nn];
        }
    };
    auto do_store = [&](int buf) {
#pragma unroll
        for (int j = 0; j < 4; j++) {
            int e = tid + (j << 7);
            int t = e >> 3, dd = e & 7;
            s_h [buf][t][dd] = rh[j];
            s_dt[buf][t][dd] = rdt[j];
            s_g [buf][t][dd] = rg[j];
        }
#pragma unroll
        for (int j = 0; j < 8; j++) {
            int e = tid + (j << 7);
            int t = e >> 4, nn = e & 15;
            s_B[buf][t][nn] = rB[j];
            s_C[buf][t][nn] = rC[j];
        }
    };

    do_load(0);
    do_store(0);
    __syncthreads();

    const int NC = Ln / SC_T;
    for (int c = 0; c < NC; c++) {
        const int buf = c & 1;
        if (c + 1 < NC) do_load(c + 1);
        const int t0 = c * SC_T;
#pragma unroll
        for (int tb = 0; tb < SC_T; tb += 8) {
            float p[8], hs[8];
#pragma unroll
            for (int tt = 0; tt < 8; tt++) {
                const int t = tb + tt;
                float dtv = s_dt[buf][t][dl];
                float hv  = s_h [buf][t][dl];
                float Bv  = s_B [buf][t][n];
                float Cv  = s_C [buf][t][n];
                float dA  = __expf(A_dn * dtv);
                state = fmaf(dA, state, Bv * hv);
                p[tt]  = state * Cv;
                hs[tt] = hv;
            }
#pragma unroll
            for (int st = 8; st >= 1; st >>= 1)
#pragma unroll
                for (int tt = 0; tt < 8; tt++)
                    p[tt] += __shfl_xor_sync(0xffffffffu, p[tt], st);
            if (n == 0) {
#pragma unroll
                for (int tt = 0; tt < 8; tt++) {
                    const int t = tb + tt;
                    float gv = s_g[buf][t][dl];
                    float yv = (p[tt] + hs[tt] * Dv) * gv * sigmoidf_(gv);
                    g_y[(size_t)(bL + t0 + t) * DIn + d] = __float2half(yv);
                }
            }
        }
        if (c + 1 < NC) do_store(buf ^ 1);
        __syncthreads();
    }
}

// ============================================================================
extern "C" void kernel_launch(void* const* d_in, const int* in_sizes, int n_in,
                              void* d_out, int out_size)
{
    const float* x          = (const float*)d_in[0];
    const float* in_proj_w  = (const float*)d_in[1];
    const float* conv_w     = (const float*)d_in[2];
    const float* conv_b     = (const float*)d_in[3];
    const float* x_proj_w   = (const float*)d_in[4];
    const float* dt_proj_w  = (const float*)d_in[5];
    const float* dt_proj_b  = (const float*)d_in[6];
    const float* out_proj_w = (const float*)d_in[7];
    const float* A_log      = (const float*)d_in[8];
    const float* D_param    = (const float*)d_in[9];
    float* out = (float*)d_out;

    float *part;
    __half *proj, *hh, *dtraw, *dt, *y, *xr, *w1t, *w2t, *w3t, *wxt;
    cudaGetSymbolAddress((void**)&proj,  g_proj);
    cudaGetSymbolAddress((void**)&hh,    g_hh);
    cudaGetSymbolAddress((void**)&dtraw, g_dtraw);
    cudaGetSymbolAddress((void**)&dt,    g_dt);
    cudaGetSymbolAddress((void**)&y,     g_y);
    cudaGetSymbolAddress((void**)&xr,    g_xr);
    cudaGetSymbolAddress((void**)&w1t,   g_w1);
    cudaGetSymbolAddress((void**)&w2t,   g_w2);
    cudaGetSymbolAddress((void**)&w3t,   g_w3);
    cudaGetSymbolAddress((void**)&wxt,   g_wx);
    cudaGetSymbolAddress((void**)&part,  g_part);

    cudaFuncSetAttribute((const void*)tgemm<0,0>, cudaFuncAttributeMaxDynamicSharedMemorySize, TG_SMEM);
    cudaFuncSetAttribute((const void*)tgemm<0,1>, cudaFuncAttributeMaxDynamicSharedMemorySize, TG_SMEM);
    cudaFuncSetAttribute((const void*)tgemm<1,1>, cudaFuncAttributeMaxDynamicSharedMemorySize, TG_SMEM);

    // 0) fused preprocessing (x -> fp16, 4 weight transposes -> fp16)
    fused_pre<<<NB_PRE, 256>>>(x, in_proj_w, dt_proj_w, out_proj_w, x_proj_w);

    // 1) proj = x @ in_proj_w   [4096,3072], K=768  (fp16 MMA, fp16 out)
    tgemm<0,1><<<dim3((2 * DIn) / 128, BLn / 128), 256, TG_SMEM>>>(
        xr, Hn, w1t, Hn, proj, 2 * DIn, Hn, nullptr, 0);

    // 2) depthwise causal conv + SiLU -> g_hh (fp16)
    conv_silu<<<(BLn / 4) * (DIn / 4) / 256, 256>>>(conv_w, conv_b);

    // 3) x_proj via fp16 MMA, split-K=8 into fp32 partials, then reduce
    tgemm<0,0><<<dim3(1, BLn / 128, XKS), 256, TG_SMEM>>>(
        hh, DIn, wxt, DIn, part, XNP, XKC, nullptr, (size_t)BLn * XNP);
    xreduce<<<(BLn * SP + 255) / 256, 256>>>();

    // 4) dt = softplus(dt_raw @ dt_proj_w + b)   (fp16 out)
    tgemm<1,1><<<dim3(DIn / 128, BLn / 128), 256, TG_SMEM>>>(
        dtraw, RnP, w2t, RnP, dt, DIn, RnP, dt_proj_b, 0);

    // 5) selective scan (+ skip + gating) -> fp16 y
    scan_kernel<<<Bn * (DIn / 8), 128>>>(A_log, D_param);

    // 6) out = y @ out_proj_w   [4096,768], K=1536  (fp32 out)
    tgemm<0,0><<<dim3(Hn / 128, BLn / 128), 256, TG_SMEM>>>(
        y, DIn, w3t, DIn, out, Hn, DIn, nullptr, 0);
}

// round 17
// speedup vs baseline: 1.4060x; 1.0795x over previous
#include <cuda_runtime.h>
#include <cuda_fp16.h>
#include <cstdint>
#include <cstddef>

#define Bn   2
#define Ln   2048
#define Hn   768
#define DIn  1536
#define Nn   16
#define Rn   48
#define RnP  64          /* dt K padded to 64 (= one BK) */
#define BLn  (Bn*Ln)     /* 4096 */
#define SP   (Rn + 2*Nn) /* 80 */
#define XNP  128         /* x_proj N padded 80 -> 128 */
#define XKS  8           /* x_proj K splits */
#define XKC  (DIn / XKS) /* 192 */

// -------- scratch (static device globals; zero-initialized at load) --------
__device__ __half g_proj [(size_t)BLn * 2 * DIn];  // in_proj output (h | gate), fp16
__device__ __half g_hh   [(size_t)BLn * DIn];      // conv+silu output, fp16
__device__ float  g_ssm  [(size_t)BLn * SP];       // x_proj output (dt_raw|B|C)
__device__ float  g_part [(size_t)XKS * BLn * XNP];// x_proj split-K partials
__device__ __half g_dtraw[(size_t)BLn * RnP];      // fp16 dt_raw, K-padded (cols 48..63 stay 0)
__device__ __half g_dt   [(size_t)BLn * DIn];      // softplus(dt), fp16
__device__ __half g_y    [(size_t)BLn * DIn];      // scan output (fp16)
__device__ __half g_xr   [(size_t)BLn * Hn];       // fp16 x
__device__ __half g_w1   [(size_t)Hn * 2 * DIn];   // in_proj_w^T  [3072][768], fp16
__device__ __half g_w2   [(size_t)DIn * RnP];      // dt_proj_w^T  [1536][64],  fp16 (pad 0)
__device__ __half g_w3   [(size_t)DIn * Hn];       // out_proj_w^T [768][1536], fp16
__device__ __half g_wx   [(size_t)XNP * DIn];      // x_proj_w^T   [128][1536], fp16 (rows 80+ zero)

__device__ __forceinline__ float sigmoidf_(float x) { return 1.f / (1.f + __expf(-x)); }
__device__ __forceinline__ float softplusf_(float x) {
    return fmaxf(x, 0.f) + log1pf(__expf(-fabsf(x)));
}
__device__ __forceinline__ void cp16s(uint32_t sa, const void* g) {
    asm volatile("cp.async.cg.shared.global [%0], [%1], 16;\n" :: "r"(sa), "l"(g));
}
__device__ __forceinline__ void cp_commit() {
    asm volatile("cp.async.commit_group;\n");
}
template<int NN>
__device__ __forceinline__ void cp_wait() {
    asm volatile("cp.async.wait_group %0;\n" :: "n"(NN));
}
__device__ __forceinline__ uint32_t smem_u32(const void* p) {
    return (uint32_t)__cvta_generic_to_shared(p);
}
__device__ __forceinline__ void ldsm_x4(uint32_t& r0, uint32_t& r1, uint32_t& r2,
                                        uint32_t& r3, uint32_t a) {
    asm volatile("ldmatrix.sync.aligned.m8n8.x4.shared.b16 {%0,%1,%2,%3}, [%4];"
                 : "=r"(r0), "=r"(r1), "=r"(r2), "=r"(r3) : "r"(a));
}
__device__ __forceinline__ uint32_t pack_h2(float a, float b) {
    __half2 h = __floats2half2_rn(a, b);
    return *(uint32_t*)&h;
}

// ============================================================================
// Fused preprocessing: one launch (x -> fp16 | 4 weight transposes -> fp16).
// ============================================================================
#define S0   ((size_t)BLn * Hn)
#define NBX  ((int)(S0 / 8 / 256))                          /* 1536 */
#define NBW1 ((2 * DIn / 32) * (Hn / 32))                    /* 2304 */
#define NBW2 ((DIn / 32) * ((Rn + 31) / 32))                 /* 96   */
#define NBW3 ((Hn / 32) * (DIn / 32))                        /* 1152 */
#define NBW4 (((SP + 31) / 32) * (DIn / 32))                 /* 144  */
#define NB_PRE (NBX + NBW1 + NBW2 + NBW3 + NBW4)

__device__ __forceinline__ void transpose_tile_h(
    const float* __restrict__ src, __half* __restrict__ dst,
    int R, int C, int Rstride, int bx, int by, float (*t)[33])
{
    const int tx = threadIdx.x & 31;
    const int ty = threadIdx.x >> 5;
#pragma unroll
    for (int i = 0; i < 32; i += 8) {
        int r = (by << 5) + ty + i, c = (bx << 5) + tx;
        if (r < R && c < C) t[ty + i][tx] = src[(size_t)r * C + c];
    }
    __syncthreads();
#pragma unroll
    for (int i = 0; i < 32; i += 8) {
        int r = (bx << 5) + ty + i, c = (by << 5) + tx;
        if (r < C && c < R) dst[(size_t)r * Rstride + c] = __float2half(t[tx][ty + i]);
    }
}

__global__ __launch_bounds__(256)
void fused_pre(const float* __restrict__ x,
               const float* __restrict__ in_proj_w,
               const float* __restrict__ dt_proj_w,
               const float* __restrict__ out_proj_w,
               const float* __restrict__ x_proj_w)
{
    __shared__ float t[32][33];
    int bid = blockIdx.x;

    if (bid < NBX) {
        size_t i = ((size_t)bid * 256 + threadIdx.x) * 8;
        float4 a = *(const float4*)(x + i);
        float4 b = *(const float4*)(x + i + 4);
        uint4 o;
        o.x = pack_h2(a.x, a.y); o.y = pack_h2(a.z, a.w);
        o.z = pack_h2(b.x, b.y); o.w = pack_h2(b.z, b.w);
        *(uint4*)(g_xr + i) = o;
        return;
    }
    bid -= NBX;
    if (bid < NBW1) {
        const int nbx = 2 * DIn / 32;
        transpose_tile_h(in_proj_w, g_w1, Hn, 2 * DIn, Hn, bid % nbx, bid / nbx, t);
        return;
    }
    bid -= NBW1;
    if (bid < NBW2) {
        const int nbx = DIn / 32;
        transpose_tile_h(dt_proj_w, g_w2, Rn, DIn, RnP, bid % nbx, bid / nbx, t);
        return;
    }
    bid -= NBW2;
    if (bid < NBW3) {
        const int nbx = Hn / 32;
        transpose_tile_h(out_proj_w, g_w3, DIn, Hn, DIn, bid % nbx, bid / nbx, t);
        return;
    }
    bid -= NBW3;
    {
        const int nbx = (SP + 31) / 32;   // 3
        transpose_tile_h(x_proj_w, g_wx, DIn, SP, DIn, bid % nbx, bid / nbx, t);
    }
}

// ============================================================================
// xreduce: sum 8 split-K partials -> g_ssm; fp16 dt_raw cols -> g_dtraw.
// ============================================================================
__global__ __launch_bounds__(256)
void xreduce()
{
    int i = blockIdx.x * blockDim.x + threadIdx.x;   // over BLn*SP
    if (i >= BLn * SP) return;
    int row = i / SP, col = i - row * SP;
    float s = 0.f;
#pragma unroll
    for (int z = 0; z < XKS; z++)
        s += g_part[(size_t)z * BLn * XNP + (size_t)row * XNP + col];
    g_ssm[i] = s;
    if (col < Rn) g_dtraw[(size_t)row * RnP + col] = __float2half(s);
}

// ============================================================================
// FP16 mma.sync GEMM (m16n8k16): 128x128 CTA, 8 warps of 64x32, BK=64,
// 3-stage cp.async, ldmatrix x4.  C[M,N] = A[M,K](lda) @ Bt[N,K](ldb)^T.
// blockIdx.z = K-split (A,Bt +z*K; C +z*csplit).
// EPI==1: C = softplus(C + bias[n]).  HOUT==1: fp16 output, else fp32.
// smem/stage: 2 tiles x 128 rows x 72 halfs = 36864 B; 3 stages = 110592 B.
// ============================================================================
#define TG_STAGES 3
#define TG_TSZ (128 * 72)                    /* halfs per operand tile */
#define TG_STG (2 * TG_TSZ)
#define TG_SMEM (TG_STAGES * TG_STG * 2)     /* 110592 bytes */

template<int EPI, int HOUT>
__global__ __launch_bounds__(256, 2)
void tgemm(const __half* __restrict__ A, int lda,
           const __half* __restrict__ Bt, int ldb,
           void* __restrict__ Cv, int N, int K,
           const float* __restrict__ bias, size_t csplit)
{
    extern __shared__ __half smem[];

    const int tid  = threadIdx.x;
    const int lane = tid & 31;
    const int warp = tid >> 5;
    const int wm   = warp >> 2;
    const int wn   = warp & 3;
    const int m0   = wm * 64;
    const int n0   = wn * 32;
    const int g    = lane >> 2;
    const int c    = lane & 3;

    const int bm = blockIdx.y << 7;
    const int bn = blockIdx.x << 7;
    const int kz = blockIdx.z;
    A  += (size_t)kz * K;
    Bt += (size_t)kz * K;

    const uint32_t smem0 = smem_u32(smem);

    // cp.async: per tile 1024 chunks of 16B (128 rows x 8 chunks); 4/thread,
    // strided ch = tid + i*256 -> row = ch>>3, kh = (ch&7)*8 halfs.
    uint32_t sOff[4];
    const __half* Ap[4];
    const __half* Bp[4];
#pragma unroll
    for (int i = 0; i < 4; i++) {
        const int ch  = tid + (i << 8);
        const int row = ch >> 3;
        const int kh  = (ch & 7) << 3;
        sOff[i] = (uint32_t)(row * 72 + kh) * 2;
        Ap[i] = A  + (size_t)(bm + row) * lda + kh;
        Bp[i] = Bt + (size_t)(bn + row) * ldb + kh;
    }

    // ldmatrix bases (stride 72 halfs = 144 B; phase banks r*4 mod 32 distinct)
    const int arow = m0 + (lane & 7) + ((lane & 8) ? 8 : 0);
    const int acol = (lane & 16) ? 8 : 0;
    const uint32_t aBase = (uint32_t)(arow * 72 + acol) * 2;
    const int brow = n0 + (lane & 7) + ((lane & 16) ? 8 : 0);
    const int bcol = (lane & 8) ? 8 : 0;
    const uint32_t bBase = (uint32_t)(brow * 72 + bcol) * 2;

    float acc[4][4][4];
#pragma unroll
    for (int i = 0; i < 4; i++)
#pragma unroll
        for (int j = 0; j < 4; j++)
#pragma unroll
            for (int q = 0; q < 4; q++) acc[i][j][q] = 0.f;

    const int nk = K >> 6;   // BK = 64 halfs

    auto load_stage = [&](int kt, int s) {
        const uint32_t stA = smem0 + (uint32_t)(s * TG_STG) * 2;
        const uint32_t stB = stA + TG_TSZ * 2;
        const int k0 = kt << 6;
#pragma unroll
        for (int i = 0; i < 4; i++) {
            cp16s(stA + sOff[i], Ap[i] + k0);
            cp16s(stB + sOff[i], Bp[i] + k0);
        }
    };
    auto compute = [&](int s) {
        const uint32_t stA = smem0 + (uint32_t)(s * TG_STG) * 2;
        const uint32_t stB = stA + TG_TSZ * 2;
#pragma unroll
        for (int ks = 0; ks < 4; ks++) {        // four k16 steps per BK=64
            const uint32_t kb = (uint32_t)(ks << 4) * 2;   // 16 halfs = 32 B
            uint32_t af[4][4], bf[4][2];
#pragma unroll
            for (int i = 0; i < 4; i++)
                ldsm_x4(af[i][0], af[i][1], af[i][2], af[i][3],
                        stA + aBase + (uint32_t)(i * 16 * 72) * 2 + kb);
#pragma unroll
            for (int jj = 0; jj < 2; jj++)
                ldsm_x4(bf[2 * jj][0], bf[2 * jj][1], bf[2 * jj + 1][0], bf[2 * jj + 1][1],
                        stB + bBase + (uint32_t)(jj * 16 * 72) * 2 + kb);
#pragma unroll
            for (int i = 0; i < 4; i++)
#pragma unroll
                for (int j = 0; j < 4; j++)
                    asm volatile(
                        "mma.sync.aligned.m16n8k16.row.col.f32.f16.f16.f32 "
                        "{%0,%1,%2,%3}, {%4,%5,%6,%7}, {%8,%9}, {%0,%1,%2,%3};\n"
                        : "+f"(acc[i][j][0]), "+f"(acc[i][j][1]),
                          "+f"(acc[i][j][2]), "+f"(acc[i][j][3])
                        : "r"(af[i][0]), "r"(af[i][1]), "r"(af[i][2]), "r"(af[i][3]),
                          "r"(bf[j][0]), "r"(bf[j][1]));
        }
    };

#pragma unroll
    for (int s = 0; s < TG_STAGES - 1; s++) {
        if (s < nk) load_stage(s, s);
        cp_commit();
    }
    for (int kt = 0; kt < nk; ++kt) {
        cp_wait<TG_STAGES - 2>();
        __syncthreads();
        const int nxt = kt + TG_STAGES - 1;
        if (nxt < nk) load_stage(nxt, nxt % TG_STAGES);
        cp_commit();
        compute(kt % TG_STAGES);
    }

    // epilogue
    float*  Cf = (float*)Cv  + (size_t)kz * csplit;
    __half* Ch = (__half*)Cv + (size_t)kz * csplit;
#pragma unroll
    for (int i = 0; i < 4; i++) {
        const int r0 = bm + m0 + i * 16 + g;
#pragma unroll
        for (int j = 0; j < 4; j++) {
            const int col = bn + n0 + j * 8 + 2 * c;
            float v00 = acc[i][j][0], v01 = acc[i][j][1];
            float v10 = acc[i][j][2], v11 = acc[i][j][3];
            if (EPI == 1) {
                const float b0v = bias[col], b1v = bias[col + 1];
                v00 = softplusf_(v00 + b0v);
                v01 = softplusf_(v01 + b1v);
                v10 = softplusf_(v10 + b0v);
                v11 = softplusf_(v11 + b1v);
            }
            if (HOUT) {
                *(uint32_t*)&Ch[(size_t)r0 * N + col]       = pack_h2(v00, v01);
                *(uint32_t*)&Ch[(size_t)(r0 + 8) * N + col] = pack_h2(v10, v11);
            } else {
                *(float2*)&Cf[(size_t)r0 * N + col]       = make_float2(v00, v01);
                *(float2*)&Cf[(size_t)(r0 + 8) * N + col] = make_float2(v10, v11);
            }
        }
    }
}

// ============================================================================
// Depthwise causal conv (K=4) + bias + SiLU. 4 channels x 4 timesteps/thread.
// ============================================================================
__global__ __launch_bounds__(256)
void conv_silu(const float* __restrict__ cw, const float* __restrict__ cb)
{
    int idx = blockIdx.x * blockDim.x + threadIdx.x;
    int d4  = (idx % (DIn / 4)) << 2;
    int bt4 = idx / (DIn / 4);
    int tb  = (bt4 & (Ln / 4 - 1)) << 2;
    size_t row0 = (size_t)bt4 * 4;

    const int s = 2 * DIn;
    const __half* p = g_proj + row0 * s + d4;
    float4 z = make_float4(0.f, 0.f, 0.f, 0.f);
    float4 r[7];
#pragma unroll
    for (int j = 0; j < 7; j++) {
        int tt = tb - 3 + j;
        if (tt >= 0) {
            uint2 u = *(const uint2*)(p + (ptrdiff_t)(j - 3) * s);
            __half2 h0 = *(__half2*)&u.x, h1 = *(__half2*)&u.y;
            float2 f0 = __half22float2(h0), f1 = __half22float2(h1);
            r[j] = make_float4(f0.x, f0.y, f1.x, f1.y);
        } else r[j] = z;
    }
    float4 cbv = *(const float4*)(cb + d4);
    float4 w0 = *(const float4*)(cw + (d4 + 0) * 4);
    float4 w1 = *(const float4*)(cw + (d4 + 1) * 4);
    float4 w2 = *(const float4*)(cw + (d4 + 2) * 4);
    float4 w3 = *(const float4*)(cw + (d4 + 3) * 4);

#pragma unroll
    for (int i = 0; i < 4; i++) {
        float4 o;
        o.x = fmaf(r[i].x, w0.x, fmaf(r[i+1].x, w0.y, fmaf(r[i+2].x, w0.z, fmaf(r[i+3].x, w0.w, cbv.x))));
        o.y = fmaf(r[i].y, w1.x, fmaf(r[i+1].y, w1.y, fmaf(r[i+2].y, w1.z, fmaf(r[i+3].y, w1.w, cbv.y))));
        o.z = fmaf(r[i].z, w2.x, fmaf(r[i+1].z, w2.y, fmaf(r[i+2].z, w2.z, fmaf(r[i+3].z, w2.w, cbv.z))));
        o.w = fmaf(r[i].w, w3.x, fmaf(r[i+1].w, w3.y, fmaf(r[i+2].w, w3.z, fmaf(r[i+3].w, w3.w, cbv.w))));
        o.x = o.x * sigmoidf_(o.x);
        o.y = o.y * sigmoidf_(o.y);
        o.z = o.z * sigmoidf_(o.z);
        o.w = o.w * sigmoidf_(o.w);
        uint2 u; u.x = pack_h2(o.x, o.y); u.y = pack_h2(o.z, o.w);
        *(uint2*)(g_hh + (row0 + i) * DIn + d4) = u;
    }
}

// ============================================================================
// Fused selective scan + skip + gating. 64-step chunks, 8-t batched shuffles.
// ============================================================================
#define SC_T 64
__global__ __launch_bounds__(128)
void scan_kernel(const float* __restrict__ Alog, const float* __restrict__ Dp)
{
    __shared__ float s_h [2][SC_T][8];
    __shared__ float s_dt[2][SC_T][8];
    __shared__ float s_g [2][SC_T][8];
    __shared__ float s_B [2][SC_T][16];
    __shared__ float s_C [2][SC_T][16];

    const int tid  = threadIdx.x;
    const int lane = tid & 31;
    const int w    = tid >> 5;
    const int n    = lane & 15;
    const int half = lane >> 4;
    const int dl   = (w << 1) + half;
    const int blk  = blockIdx.x;
    const int b    = blk / (DIn / 8);
    const int d0   = (blk % (DIn / 8)) << 3;
    const int d    = d0 + dl;
    const int bL   = b * Ln;

    const float A_dn = -__expf(Alog[d * Nn + n]);
    const float Dv   = Dp[d];
    float state = 0.f;

    float rh[4], rdt[4], rg[4], rB[8], rC[8];

    auto do_load = [&](int c) {
        int t0 = c * SC_T;
#pragma unroll
        for (int j = 0; j < 4; j++) {
            int e = tid + (j << 7);
            int t = e >> 3, dd = e & 7;
            int row = bL + t0 + t;
            rh[j]  = __half2float(g_hh [(size_t)row * DIn + d0 + dd]);
            rdt[j] = __half2float(g_dt [(size_t)row * DIn + d0 + dd]);
            rg[j]  = __half2float(g_proj[(size_t)row * (2 * DIn) + DIn + d0 + dd]);
        }
#pragma unroll
        for (int j = 0; j < 8; j++) {
            int e = tid + (j << 7);
            int t = e >> 4, nn = e & 15;
            int row = bL + t0 + t;
            rB[j] = g_ssm[(size_t)row * SP + Rn + nn];
            rC[j] = g_ssm[(size_t)row * SP + Rn + Nn + nn];
        }
    };
    auto do_store = [&](int buf) {
#pragma unroll
        for (int j = 0; j < 4; j++) {
            int e = tid + (j << 7);
            int t = e >> 3, dd = e & 7;
            s_h [buf][t][dd] = rh[j];
            s_dt[buf][t][dd] = rdt[j];
            s_g [buf][t][dd] = rg[j];
        }
#pragma unroll
        for (int j = 0; j < 8; j++) {
            int e = tid + (j << 7);
            int t = e >> 4, nn = e & 15;
            s_B[buf][t][nn] = rB[j];
            s_C[buf][t][nn] = rC[j];
        }
    };

    do_load(0);
    do_store(0);
    __syncthreads();

    const int NC = Ln / SC_T;
    for (int c = 0; c < NC; c++) {
        const int buf = c & 1;
        if (c + 1 < NC) do_load(c + 1);
        const int t0 = c * SC_T;
#pragma unroll
        for (int tb = 0; tb < SC_T; tb += 8) {
            float p[8], hs[8];
#pragma unroll
            for (int tt = 0; tt < 8; tt++) {
                const int t = tb + tt;
                float dtv = s_dt[buf][t][dl];
                float hv  = s_h [buf][t][dl];
                float Bv  = s_B [buf][t][n];
                float Cv  = s_C [buf][t][n];
                float dA  = __expf(A_dn * dtv);
                state = fmaf(dA, state, Bv * hv);
                p[tt]  = state * Cv;
                hs[tt] = hv;
            }
#pragma unroll
            for (int st = 8; st >= 1; st >>= 1)
#pragma unroll
                for (int tt = 0; tt < 8; tt++)
                    p[tt] += __shfl_xor_sync(0xffffffffu, p[tt], st);
            if (n == 0) {
#pragma unroll
                for (int tt = 0; tt < 8; tt++) {
                    const int t = tb + tt;
                    float gv = s_g[buf][t][dl];
                    float yv = (p[tt] + hs[tt] * Dv) * gv * sigmoidf_(gv);
                    g_y[(size_t)(bL + t0 + t) * DIn + d] = __float2half(yv);
                }
            }
        }
        if (c + 1 < NC) do_store(buf ^ 1);
        __syncthreads();
    }
}

// ============================================================================
extern "C" void kernel_launch(void* const* d_in, const int* in_sizes, int n_in,
                              void* d_out, int out_size)
{
    const float* x          = (const float*)d_in[0];
    const float* in_proj_w  = (const float*)d_in[1];
    const float* conv_w     = (const float*)d_in[2];
    const float* conv_b     = (const float*)d_in[3];
    const float* x_proj_w   = (const float*)d_in[4];
    const float* dt_proj_w  = (const float*)d_in[5];
    const float* dt_proj_b  = (const float*)d_in[6];
    const float* out_proj_w = (const float*)d_in[7];
    const float* A_log      = (const float*)d_in[8];
    const float* D_param    = (const float*)d_in[9];
    float* out = (float*)d_out;

    float *part;
    __half *proj, *hh, *dtraw, *dt, *y, *xr, *w1t, *w2t, *w3t, *wxt;
    cudaGetSymbolAddress((void**)&proj,  g_proj);
    cudaGetSymbolAddress((void**)&hh,    g_hh);
    cudaGetSymbolAddress((void**)&dtraw, g_dtraw);
    cudaGetSymbolAddress((void**)&dt,    g_dt);
    cudaGetSymbolAddress((void**)&y,     g_y);
    cudaGetSymbolAddress((void**)&xr,    g_xr);
    cudaGetSymbolAddress((void**)&w1t,   g_w1);
    cudaGetSymbolAddress((void**)&w2t,   g_w2);
    cudaGetSymbolAddress((void**)&w3t,   g_w3);
    cudaGetSymbolAddress((void**)&wxt,   g_wx);
    cudaGetSymbolAddress((void**)&part,  g_part);

    cudaFuncSetAttribute((const void*)tgemm<0,0>, cudaFuncAttributeMaxDynamicSharedMemorySize, TG_SMEM);
    cudaFuncSetAttribute((const void*)tgemm<0,1>, cudaFuncAttributeMaxDynamicSharedMemorySize, TG_SMEM);
    cudaFuncSetAttribute((const void*)tgemm<1,1>, cudaFuncAttributeMaxDynamicSharedMemorySize, TG_SMEM);

    // 0) fused preprocessing (x -> fp16, 4 weight transposes -> fp16)
    fused_pre<<<NB_PRE, 256>>>(x, in_proj_w, dt_proj_w, out_proj_w, x_proj_w);

    // 1) proj = x @ in_proj_w   [4096,3072], K=768  (fp16 MMA, fp16 out)
    tgemm<0,1><<<dim3((2 * DIn) / 128, BLn / 128), 256, TG_SMEM>>>(
        xr, Hn, w1t, Hn, proj, 2 * DIn, Hn, nullptr, 0);

    // 2) depthwise causal conv + SiLU -> g_hh (fp16)
    conv_silu<<<(BLn / 4) * (DIn / 4) / 256, 256>>>(conv_w, conv_b);

    // 3) x_proj via fp16 MMA, split-K=8 into fp32 partials, then reduce
    tgemm<0,0><<<dim3(1, BLn / 128, XKS), 256, TG_SMEM>>>(
        hh, DIn, wxt, DIn, part, XNP, XKC, nullptr, (size_t)BLn * XNP);
    xreduce<<<(BLn * SP + 255) / 256, 256>>>();

    // 4) dt = softplus(dt_raw @ dt_proj_w + b)   (fp16 out, K=64 = one BK)
    tgemm<1,1><<<dim3(DIn / 128, BLn / 128), 256, TG_SMEM>>>(
        dtraw, RnP, w2t, RnP, dt, DIn, RnP, dt_proj_b, 0);

    // 5) selective scan (+ skip + gating) -> fp16 y
    scan_kernel<<<Bn * (DIn / 8), 128>>>(A_log, D_param);

    // 6) out = y @ out_proj_w   [4096,768], K=1536  (fp32 out)
    tgemm<0,0><<<dim3(Hn / 128, BLn / 128), 256, TG_SMEM>>>(
        y, DIn, w3t, DIn, out, Hn, DIn, nullptr, 0);
}